// round 14
// baseline (speedup 1.0000x reference)
#include <cuda_runtime.h>
#include <cuda_fp16.h>
#include <mma.h>
#include <cstdint>
#include <math.h>

using namespace nvcuda;

#define HH 12
#define NP 196
#define FF 8
#define DIMM 768
#define D3 192
#define BB 8
#define SS 1569
#define PP 195
#define C3 2304
#define C3X 6912            // fused QKV row width
#define OQ 0
#define OK 2304
#define OV 4608
#define SCALE_INV (1.0f/96.0f)

#define M1PAD 12672
#define M2PAD 1664

// ---------------- scratch (device globals; zero-initialized) ----------------
__device__ __half g_qkvh[BB*SS*C3X];
__device__ __half g_q2kvh[BB*PP*C3X];
__device__ __half g_t1h[M2PAD*C3];
__device__ __half g_tih[M2PAD*DIMM];
__device__ __half g_xh[M1PAD*DIMM];
__device__ float g_cls[BB*C3];
__device__ float g_t2[BB*FF*C3];
__device__ float g_rows[BB*9*DIMM];
__device__ float g_bqkv[C3X];
__device__ __half g_Wh[C3X*DIMM];
__device__ __half g_Wth[DIMM*C3];

// ---------------- helpers ------------------------------------------------------
__device__ __forceinline__ uint32_t smem_u32(const void* p) {
    uint32_t a;
    asm("{ .reg .u64 t; cvta.to.shared.u64 t, %1; cvt.u32.u64 %0, t; }" : "=r"(a) : "l"(p));
    return a;
}
#define CP_ASYNC16(dst_u32, src_ptr) \
    asm volatile("cp.async.cg.shared.global [%0], [%1], 16;" :: "r"(dst_u32), "l"(src_ptr))
#define CP_COMMIT() asm volatile("cp.async.commit_group;" ::: "memory")
#define CP_WAIT1()  asm volatile("cp.async.wait_group 1;" ::: "memory")

// ---------------- fp32 -> fp16 -----------------------------------------------------
__global__ void tohalf(const float* __restrict__ in, __half* __restrict__ out, int n4) {
    int i = blockIdx.x * blockDim.x + threadIdx.x;
    if (i >= n4) return;
    float4 v = ((const float4*)in)[i];
    ((__half2*)out)[i * 2 + 0] = __floats2half2_rn(v.x, v.y);
    ((__half2*)out)[i * 2 + 1] = __floats2half2_rn(v.z, v.w);
}

// ---------------- transpose to fp16: [K,N] -> [N,K] --------------------------------
__global__ void transpose_h(const float* __restrict__ in, __half* __restrict__ outh,
                            int K, int N) {
    __shared__ float t[32][33];
    const int n0 = blockIdx.x * 32, k0 = blockIdx.y * 32;
    const int tx = threadIdx.x & 31, ty = threadIdx.x >> 5;
#pragma unroll
    for (int i = 0; i < 32; i += 8)
        t[ty + i][tx] = in[(size_t)(k0 + ty + i) * N + n0 + tx];
    __syncthreads();
#pragma unroll
    for (int i = 0; i < 32; i += 8)
        outh[(size_t)(n0 + ty + i) * K + k0 + tx] = __float2half(t[tx][ty + i]);
}

// ---------------- bias concat --------------------------------------------------------
__global__ void concat_bias(const float* __restrict__ bq, const float* __restrict__ bk,
                            const float* __restrict__ bv, float* __restrict__ outb) {
    int i = blockIdx.x * blockDim.x + threadIdx.x;
    if (i >= C3X) return;
    outb[i] = (i < OK) ? bq[i] : (i < OV) ? bk[i - OK] : bv[i - OV];
}

// ================= fp16 1-pass HMMA GEMM, BK=32, 2-stage, 2 CTA/SM =================
#define LDT 40
#define HT (128 * LDT * 2)
#define HSTAGE (2 * HT)
#define H_SMEM 65536

__global__ void __launch_bounds__(256, 2)
gemm_h1(const __half* __restrict__ A, const __half* __restrict__ B_g,
        const float* __restrict__ bias, __half* __restrict__ C,
        int M, int N, int K) {
    extern __shared__ char smem[];
    const uint32_t smem_b = smem_u32(smem);
    const int tid = threadIdx.x;
    const int wid = tid >> 5;
    const int wm = wid & 3, wn = wid >> 2;
    const int rowA0 = blockIdx.y * 128;
    const int n0 = blockIdx.x * 128;
    const int nch = K >> 5;

    const int r_cp = tid >> 1;
    const int s_cp = (tid & 1) * 2;
    const __half* srcA = A   + (size_t)(rowA0 + r_cp) * K + s_cp * 8;
    const __half* srcB = B_g + (size_t)(n0 + r_cp) * K + s_cp * 8;
    const uint32_t dst_row = smem_b + r_cp * (LDT * 2) + s_cp * 16;

    auto issue_stage = [&](int c, int buf) {
        const int k0 = c << 5;
        const uint32_t sb = buf * HSTAGE;
        CP_ASYNC16(dst_row + sb, srcA + k0);
        CP_ASYNC16(dst_row + sb + 16, srcA + k0 + 8);
        CP_ASYNC16(dst_row + sb + HT, srcB + k0);
        CP_ASYNC16(dst_row + sb + HT + 16, srcB + k0 + 8);
    };

    wmma::fragment<wmma::accumulator, 16, 16, 16, float> acc[2][4];
#pragma unroll
    for (int i = 0; i < 2; i++)
#pragma unroll
        for (int j = 0; j < 4; j++) wmma::fill_fragment(acc[i][j], 0.f);

    issue_stage(0, 0);
    CP_COMMIT();

    for (int c = 0; c < nch; c++) {
        if (c + 1 < nch) issue_stage(c + 1, (c + 1) & 1);
        CP_COMMIT();
        CP_WAIT1();
        __syncthreads();

        const __half* Ah = (const __half*)(smem + (c & 1) * HSTAGE);
        const __half* Bh = Ah + 128 * LDT;
#pragma unroll
        for (int kk = 0; kk < 32; kk += 16) {
            wmma::fragment<wmma::matrix_a, 16, 16, 16, __half, wmma::row_major> ah[2];
#pragma unroll
            for (int i = 0; i < 2; i++)
                wmma::load_matrix_sync(ah[i], Ah + (wm * 32 + i * 16) * LDT + kk, LDT);
#pragma unroll
            for (int j = 0; j < 4; j++) {
                wmma::fragment<wmma::matrix_b, 16, 16, 16, __half, wmma::col_major> bh;
                wmma::load_matrix_sync(bh, Bh + (wn * 64 + j * 16) * LDT + kk, LDT);
                wmma::mma_sync(acc[0][j], ah[0], bh, acc[0][j]);
                wmma::mma_sync(acc[1][j], ah[1], bh, acc[1][j]);
            }
        }
        __syncthreads();
    }

    float* sC = (float*)smem;
#pragma unroll
    for (int i = 0; i < 2; i++)
#pragma unroll
        for (int j = 0; j < 4; j++)
            wmma::store_matrix_sync(sC + (wm * 32 + i * 16) * 128 + wn * 64 + j * 16,
                                    acc[i][j], 128, wmma::mem_row_major);
    __syncthreads();
#pragma unroll
    for (int i = 0; i < 16; i++) {
        const int f = i * 256 + tid;
        const int r = f >> 5, c4 = f & 31;
        const int gm = rowA0 + r;
        if (gm < M) {
            float4 v = *(float4*)(sC + r * 128 + c4 * 4);
            const int n = n0 + c4 * 4;
            __half2 h0 = __floats2half2_rn(v.x + bias[n + 0], v.y + bias[n + 1]);
            __half2 h1 = __floats2half2_rn(v.z + bias[n + 2], v.w + bias[n + 3]);
            uint2 u;
            u.x = *(uint32_t*)&h0;
            u.y = *(uint32_t*)&h1;
            *(uint2*)(C + (size_t)gm * N + n) = u;
        }
    }
}

// ---------------- inter_cls (fp16 qkv reads) ------------------------------------------
__global__ void inter_cls_kernel() {
    __shared__ float sc[SS];
    __shared__ float red[256];
    __shared__ float part[8 * D3];
    const int h = blockIdx.x, b = blockIdx.y;
    const int tid = threadIdx.x, lane = tid & 31, wid = tid >> 5;
    const __half* baseq = g_qkvh + (size_t)b * SS * C3X + OQ + h * D3;
    const __half* basek = g_qkvh + (size_t)b * SS * C3X + OK + h * D3;
    const __half* basev = g_qkvh + (size_t)b * SS * C3X + OV + h * D3;

    float2 qv[3];
#pragma unroll
    for (int i = 0; i < 3; i++)
        qv[i] = __half22float2(((const __half2*)baseq)[lane + 32 * i]);

    for (int t = wid; t < SS; t += 8) {
        const __half2* kr = (const __half2*)(basek + (size_t)t * C3X);
        float p = 0.f;
#pragma unroll
        for (int i = 0; i < 3; i++) {
            float2 kv = __half22float2(kr[lane + 32 * i]);
            p += qv[i].x * kv.x + qv[i].y * kv.y;
        }
#pragma unroll
        for (int off = 16; off; off >>= 1) p += __shfl_xor_sync(0xffffffffu, p, off);
        if (lane == 0) sc[t] = p * SCALE_INV;
    }
    __syncthreads();

    float m = -1e30f;
    for (int t = tid; t < SS; t += 256) m = fmaxf(m, sc[t]);
    red[tid] = m; __syncthreads();
    for (int s = 128; s; s >>= 1) { if (tid < s) red[tid] = fmaxf(red[tid], red[tid + s]); __syncthreads(); }
    m = red[0]; __syncthreads();

    float z = 0.f;
    for (int t = tid; t < SS; t += 256) { float e = expf(sc[t] - m); sc[t] = e; z += e; }
    red[tid] = z; __syncthreads();
    for (int s = 128; s; s >>= 1) { if (tid < s) red[tid] += red[tid + s]; __syncthreads(); }
    const float invZ = 1.f / red[0];
    __syncthreads();

    float2 a[3] = {{0.f,0.f},{0.f,0.f},{0.f,0.f}};
    for (int t = wid; t < SS; t += 8) {
        const float p = sc[t];
        const __half2* vr = (const __half2*)(basev + (size_t)t * C3X);
#pragma unroll
        for (int i = 0; i < 3; i++) {
            float2 vv = __half22float2(vr[lane + 32 * i]);
            a[i].x += p * vv.x;
            a[i].y += p * vv.y;
        }
    }
#pragma unroll
    for (int i = 0; i < 3; i++) {
        const int j0 = 2 * (lane + 32 * i);
        part[wid * D3 + j0] = a[i].x;
        part[wid * D3 + j0 + 1] = a[i].y;
    }
    __syncthreads();
    if (tid < D3) {
        float s = 0.f;
#pragma unroll
        for (int w = 0; w < 8; w++) s += part[w * D3 + tid];
        g_cls[b * C3 + h * D3 + tid] = s * invZ;
    }
}

// ---------------- temporal attention (fp16 in/out) ------------------------------------
__global__ void temporal_kernel() {
    __shared__ float qs[8 * 193];
    __shared__ float ks[8 * 193];
    __shared__ float sc[8 * 9];
    __shared__ float cw[8];
    const int p = blockIdx.x, h = blockIdx.y, b = blockIdx.z;
    const int tid = threadIdx.x;
    const size_t bb = (size_t)b * SS * C3X;

    for (int e = tid; e < 8 * 96; e += 192) {
        int f = e / 96, j2 = e - f * 96;
        int tok = f * NP + p + 2;
        const __half2* qrow = (const __half2*)(g_qkvh + bb + (size_t)tok * C3X + OQ + h * D3);
        const __half2* krow = (const __half2*)(g_qkvh + bb + (size_t)tok * C3X + OV + h * D3);
        float2 qv = __half22float2(qrow[j2]);
        float2 kv = __half22float2(krow[j2]);
        qs[f * 193 + 2 * j2] = qv.x; qs[f * 193 + 2 * j2 + 1] = qv.y;
        ks[f * 193 + 2 * j2] = kv.x; ks[f * 193 + 2 * j2 + 1] = kv.y;
    }
    __syncthreads();

    if (tid < 64) {
        int f = tid >> 3, g = tid & 7;
        float s = 0.f;
        for (int j = 0; j < D3; j++) s += qs[f * 193 + j] * ks[g * 193 + j];
        sc[f * 9 + g] = s * SCALE_INV;
    }
    __syncthreads();

    if (tid < 8) {
        int f = tid;
        float mx = -1e30f;
        for (int g = 0; g < 8; g++) mx = fmaxf(mx, sc[f * 9 + g]);
        float z = 0.f;
        for (int g = 0; g < 8; g++) { float e = expf(sc[f * 9 + g] - mx); sc[f * 9 + g] = e; z += e; }
        float inv = 1.f / z;
        for (int g = 0; g < 8; g++) sc[f * 9 + g] *= inv;
    }
    __syncthreads();
    if (tid < 8) {
        int g = tid;
        float s = 0.f;
        for (int f = 0; f < 8; f++) s += sc[f * 9 + g];
        cw[g] = s;
    }
    __syncthreads();

    {
        int d = tid;
        float acc = 0.f;
#pragma unroll
        for (int g = 0; g < 8; g++) {
            int tok = g * NP + p + 2;
            acc += cw[g] * __half2float(g_qkvh[bb + (size_t)tok * C3X + OK + h * D3 + d]);
        }
        g_t1h[((size_t)b * PP + p) * C3 + h * D3 + d] = __float2half(acc);
    }
}

// ======== out_attn xi=0 (nk=196): K in smem fp16, q in regs, shuffle reduce ==========
// one block per (h,b); 256 threads; dyn smem: Kh[196*96 half2] | w[196] | sbuf[8][4][196]
#define OA_KH_B   (196 * 96 * 4)                // 75264
#define OA_W_OFF  OA_KH_B                       // 75264
#define OA_SB_OFF (OA_W_OFF + 784)              // 76048
#define OA_SMEM   (OA_SB_OFF + 8 * 4 * 196 * 4) // 101136

__global__ void out_attn196_kernel() {
    extern __shared__ char sm8[];
    __half2* Kh = (__half2*)sm8;
    float* w = (float*)(sm8 + OA_W_OFF);
    float* sbuf = (float*)(sm8 + OA_SB_OFF);
    const int h = blockIdx.x, b = blockIdx.y;
    const int tid = threadIdx.x, lane = tid & 31, wid = tid >> 5;
    const size_t rbase = (size_t)b * PP * C3X + h * D3;

    for (int e = tid; e < 196 * 96; e += 256) {
        int r = e / 96, j2 = e - r * 96;
        int kp = r % PP;
        Kh[r * 96 + j2] = *(const __half2*)(g_q2kvh + rbase + (size_t)kp * C3X + OV + 2 * j2);
    }
    for (int k = tid; k < 196; k += 256) w[k] = 0.f;
    __syncthreads();

    float* sb = sbuf + wid * 784;
    for (int p = 0; p < 7; p++) {
        const int base = p * 32 + wid * 4;
        float2 qr[4][3];
#pragma unroll
        for (int t = 0; t < 4; t++) {
            const int q = base + t;
            const int qp = (q < 196) ? (q % PP) : 0;
            const __half2* qrow = (const __half2*)(g_q2kvh + rbase + (size_t)qp * C3X + OQ);
#pragma unroll
            for (int i = 0; i < 3; i++)
                qr[t][i] = (q < 196) ? __half22float2(qrow[lane + 32 * i]) : make_float2(0.f, 0.f);
        }
        for (int k = 0; k < 196; k++) {
            const __half2* kr = Kh + k * 96;
            const float2 k0 = __half22float2(kr[lane]);
            const float2 k1 = __half22float2(kr[lane + 32]);
            const float2 k2 = __half22float2(kr[lane + 64]);
            float s0 = qr[0][0].x*k0.x + qr[0][0].y*k0.y + qr[0][1].x*k1.x + qr[0][1].y*k1.y + qr[0][2].x*k2.x + qr[0][2].y*k2.y;
            float s1 = qr[1][0].x*k0.x + qr[1][0].y*k0.y + qr[1][1].x*k1.x + qr[1][1].y*k1.y + qr[1][2].x*k2.x + qr[1][2].y*k2.y;
            float s2 = qr[2][0].x*k0.x + qr[2][0].y*k0.y + qr[2][1].x*k1.x + qr[2][1].y*k1.y + qr[2][2].x*k2.x + qr[2][2].y*k2.y;
            float s3 = qr[3][0].x*k0.x + qr[3][0].y*k0.y + qr[3][1].x*k1.x + qr[3][1].y*k1.y + qr[3][2].x*k2.x + qr[3][2].y*k2.y;
#pragma unroll
            for (int off = 16; off; off >>= 1) {
                s0 += __shfl_xor_sync(0xffffffffu, s0, off);
                s1 += __shfl_xor_sync(0xffffffffu, s1, off);
                s2 += __shfl_xor_sync(0xffffffffu, s2, off);
                s3 += __shfl_xor_sync(0xffffffffu, s3, off);
            }
            if (lane == 0) {
                sb[k] = s0; sb[196 + k] = s1; sb[392 + k] = s2; sb[588 + k] = s3;
            }
        }
        __syncwarp();
#pragma unroll
        for (int t = 0; t < 4; t++) {
            const int q = base + t;
            if (q >= 196) break;
            const float* row = sb + t * 196;
            float sv[7];
            float mx = -1e30f;
#pragma unroll
            for (int c = 0; c < 7; c++) {
                const int kk = lane + 32 * c;
                sv[c] = (kk < 196) ? row[kk] * SCALE_INV : -1e30f;
                mx = fmaxf(mx, sv[c]);
            }
#pragma unroll
            for (int off = 16; off; off >>= 1) mx = fmaxf(mx, __shfl_xor_sync(0xffffffffu, mx, off));
            float z = 0.f;
#pragma unroll
            for (int c = 0; c < 7; c++) {
                const int kk = lane + 32 * c;
                sv[c] = (kk < 196) ? expf(sv[c] - mx) : 0.f;
                z += sv[c];
            }
#pragma unroll
            for (int off = 16; off; off >>= 1) z += __shfl_xor_sync(0xffffffffu, z, off);
            const float inv = 1.f / z;
#pragma unroll
            for (int c = 0; c < 7; c++) {
                const int kk = lane + 32 * c;
                if (kk < 196) atomicAdd(&w[kk], sv[c] * inv);
            }
        }
        __syncwarp();
    }
    __syncthreads();

    if (tid < D3) {
        float acc = 0.f;
        for (int k = 0; k < 196; k++) {
            const int kp = k % PP;
            acc += w[k] * __half2float(g_q2kvh[rbase + (size_t)kp * C3X + OK + tid]);
        }
        g_t2[((size_t)b * FF) * C3 + h * D3 + tid] = acc;
    }
}

// ---------------- output-stage attention (nk=8 path, unchanged) ------------------------
__global__ void out_attn_kernel(int xi_base, int nk) {
    extern __shared__ float sm[];
    float* Kb = sm;
    float* qb = sm + nk * 193;
    float* w  = qb + 8 * D3;
    const int xi = xi_base + blockIdx.x;
    const int h = blockIdx.y, b = blockIdx.z;
    const int tid = threadIdx.x, lane = tid & 31, wid = tid >> 5;
    const size_t rbase = (size_t)b * PP * C3X + h * D3;
    const int CNT = (nk + 31) >> 5;

    for (int e = tid; e < nk * 96; e += 256) {
        int r = e / 96, j2 = e - r * 96;
        int kp = (nk == 196) ? (r % PP) : (xi + r);
        float2 v = __half22float2(
            *(const __half2*)(g_q2kvh + rbase + (size_t)kp * C3X + OV + 2 * j2));
        Kb[r * 193 + 2 * j2] = v.x;
        Kb[r * 193 + 2 * j2 + 1] = v.y;
    }
    for (int k = tid; k < nk; k += 256) w[k] = 0.f;
    __syncthreads();

    for (int q = wid; q < 196; q += 8) {
        int qp = (xi + q) % PP;
        for (int j2 = lane; j2 < 96; j2 += 32) {
            float2 v = __half22float2(
                *(const __half2*)(g_q2kvh + rbase + (size_t)qp * C3X + OQ + 2 * j2));
            qb[wid * D3 + 2 * j2] = v.x;
            qb[wid * D3 + 2 * j2 + 1] = v.y;
        }
        __syncwarp();

        float s[7];
        int cnt = 0;
        const int kbase = lane * CNT;
        for (int c = 0; c < CNT; c++) {
            const int k = kbase + c;
            if (k < nk) {
                float d = 0.f;
                const float* kr = Kb + k * 193;
                const float* qr = qb + wid * D3;
                for (int j = 0; j < D3; j++) d += qr[j] * kr[j];
                s[cnt++] = d * SCALE_INV;
            }
        }
        float mx = -1e30f;
        for (int c = 0; c < cnt; c++) mx = fmaxf(mx, s[c]);
#pragma unroll
        for (int off = 16; off; off >>= 1) mx = fmaxf(mx, __shfl_xor_sync(0xffffffffu, mx, off));
        float z = 0.f;
        for (int c = 0; c < cnt; c++) { float e = expf(s[c] - mx); s[c] = e; z += e; }
#pragma unroll
        for (int off = 16; off; off >>= 1) z += __shfl_xor_sync(0xffffffffu, z, off);
        float inv = 1.f / z;
        for (int c = 0; c < cnt; c++) atomicAdd(&w[kbase + c], s[c] * inv);
        __syncwarp();
    }
    __syncthreads();

    if (tid < D3) {
        float acc = 0.f;
        for (int k = 0; k < nk; k++) {
            int kp = (nk == 196) ? (k % PP) : (xi + k);
            acc += w[k] * __half2float(g_q2kvh[rbase + (size_t)kp * C3X + OK + tid]);
        }
        g_t2[((size_t)b * FF + xi) * C3 + h * D3 + tid] = acc;
    }
}

// ---------------- final 9 rows per batch ------------------------------------------------
__global__ void final_rows_kernel(const float* __restrict__ Wf, const float* __restrict__ bf) {
    extern __shared__ float As[];
    const int cb = blockIdx.x, b = blockIdx.y;
    const int tid = threadIdx.x;
    for (int e = tid; e < 9 * C3; e += 192) {
        int r = e / C3, k = e - r * C3;
        As[e] = (r == 0) ? g_cls[b * C3 + k] : g_t2[((size_t)b * FF + (r - 1)) * C3 + k];
    }
    __syncthreads();
    const int c = cb * 192 + tid;
    float acc[9];
#pragma unroll
    for (int r = 0; r < 9; r++) acc[r] = 0.f;
    for (int k = 0; k < C3; k++) {
        float wv = Wf[(size_t)k * DIMM + c];
#pragma unroll
        for (int r = 0; r < 9; r++) acc[r] += As[r * C3 + k] * wv;
    }
    float bv = bf[c];
#pragma unroll
    for (int r = 0; r < 9; r++)
        g_rows[((size_t)b * 9 + r) * DIMM + c] = acc[r] + bv;
}

// ---------------- broadcast -> output -----------------------------------------------------
__global__ void bcast_kernel(float* __restrict__ out) {
    size_t i4 = (size_t)blockIdx.x * blockDim.x + threadIdx.x;
    const size_t total4 = (size_t)BB * SS * DIMM / 4;
    if (i4 >= total4) return;
    size_t idx = i4 * 4;
    int c = idx % DIMM;
    size_t rs = idx / DIMM;
    int s = rs % SS;
    int b = rs / SS;
    int r = (s == 0) ? 0 : 1 + ((s - 1) & 7);
    ((float4*)out)[i4] = *(const float4*)(g_rows + ((size_t)b * 9 + r) * DIMM + c);
}

// ---------------- launch ------------------------------------------------------------------
extern "C" void kernel_launch(void* const* d_in, const int* in_sizes, int n_in,
                              void* d_out, int out_size) {
    const float* x  = (const float*)d_in[0];
    const float* Wq = (const float*)d_in[1];
    const float* bq = (const float*)d_in[2];
    const float* Wk = (const float*)d_in[3];
    const float* bk = (const float*)d_in[4];
    const float* Wv = (const float*)d_in[5];
    const float* bv = (const float*)d_in[6];
    const float* Wt = (const float*)d_in[7];
    const float* bt = (const float*)d_in[8];
    const float* Wf = (const float*)d_in[9];
    const float* bf = (const float*)d_in[10];
    float* out = (float*)d_out;

    float *p_bqkv;
    cudaGetSymbolAddress((void**)&p_bqkv, g_bqkv);
    __half *p_qkvh, *p_q2kvh, *p_t1h, *p_tih, *p_xh, *p_Wh, *p_Wth;
    cudaGetSymbolAddress((void**)&p_qkvh, g_qkvh);
    cudaGetSymbolAddress((void**)&p_q2kvh, g_q2kvh);
    cudaGetSymbolAddress((void**)&p_t1h, g_t1h);
    cudaGetSymbolAddress((void**)&p_tih, g_tih);
    cudaGetSymbolAddress((void**)&p_xh, g_xh);
    cudaGetSymbolAddress((void**)&p_Wh, g_Wh);
    cudaGetSymbolAddress((void**)&p_Wth, g_Wth);

    cudaFuncSetAttribute(gemm_h1, cudaFuncAttributeMaxDynamicSharedMemorySize, H_SMEM);
    cudaFuncSetAttribute(out_attn_kernel, cudaFuncAttributeMaxDynamicSharedMemorySize, 160000);
    cudaFuncSetAttribute(out_attn196_kernel, cudaFuncAttributeMaxDynamicSharedMemorySize, OA_SMEM);
    cudaFuncSetAttribute(final_rows_kernel, cudaFuncAttributeMaxDynamicSharedMemorySize, 9 * C3 * 4);

    // fused weight transpose -> [6912, 768] fp16
    transpose_h<<<dim3(C3 / 32, DIMM / 32), 256>>>(Wq, p_Wh + (size_t)OQ * DIMM, DIMM, C3);
    transpose_h<<<dim3(C3 / 32, DIMM / 32), 256>>>(Wk, p_Wh + (size_t)OK * DIMM, DIMM, C3);
    transpose_h<<<dim3(C3 / 32, DIMM / 32), 256>>>(Wv, p_Wh + (size_t)OV * DIMM, DIMM, C3);
    transpose_h<<<dim3(DIMM / 32, C3 / 32), 256>>>(Wt, p_Wth, C3, DIMM);
    concat_bias<<<(C3X + 255) / 256, 256>>>(bq, bk, bv, p_bqkv);
    {
        int n4 = BB * SS * DIMM / 4;
        tohalf<<<(n4 + 255) / 256, 256>>>(x, p_xh, n4);
    }

    const int M1 = BB * SS;   // 12552
    {
        dim3 grid(C3X / 128, M1PAD / 128);
        gemm_h1<<<grid, 256, H_SMEM>>>(p_xh, p_Wh, p_bqkv, p_qkvh, M1, C3X, DIMM);
    }
    inter_cls_kernel<<<dim3(HH, BB), 256>>>();
    temporal_kernel<<<dim3(PP, HH, BB), 192>>>();

    const int M2 = BB * PP;   // 1560
    {
        dim3 grid(DIMM / 128, M2PAD / 128);
        gemm_h1<<<grid, 256, H_SMEM>>>(p_t1h, p_Wth, bt, p_tih, M2, DIMM, C3);
    }
    {
        dim3 grid(C3X / 128, M2PAD / 128);
        gemm_h1<<<grid, 256, H_SMEM>>>(p_tih, p_Wh, p_bqkv, p_q2kvh, M2, C3X, DIMM);
    }
    {
        out_attn196_kernel<<<dim3(HH, BB), 256, OA_SMEM>>>();
        size_t smB = (size_t)(8 * 193 + 8 * D3 + 8) * 4;
        out_attn_kernel<<<dim3(7, HH, BB), 256, smB>>>(1, 8);
    }
    final_rows_kernel<<<dim3(4, BB), 192, (size_t)9 * C3 * 4>>>(Wf, bf);
    {
        const size_t total4 = (size_t)BB * SS * DIMM / 4;
        bcast_kernel<<<(unsigned)((total4 + 255) / 256), 256>>>(out);
    }
}

// round 15
// speedup vs baseline: 1.1207x; 1.1207x over previous
#include <cuda_runtime.h>
#include <cuda_fp16.h>
#include <mma.h>
#include <cstdint>
#include <math.h>

using namespace nvcuda;

#define HH 12
#define NP 196
#define FF 8
#define DIMM 768
#define D3 192
#define BB 8
#define SS 1569
#define PP 195
#define C3 2304
#define C3X 6912
#define OQ 0
#define OK 2304
#define OV 4608
#define SCALE_INV (1.0f/96.0f)

#define M1PAD 12672
#define M2PAD 1664

// ---------------- scratch (device globals; zero-initialized) ----------------
__device__ __half g_qkvh[BB*SS*C3X];
__device__ __half g_q2kvh[BB*PP*C3X];
__device__ __half g_t1h[M2PAD*C3];
__device__ __half g_tih[M2PAD*DIMM];
__device__ __half g_xh[M1PAD*DIMM];
__device__ float g_cls[BB*C3];
__device__ float g_t2[BB*FF*C3];
__device__ float g_rows[BB*9*DIMM];
__device__ float g_bqkv[C3X];
__device__ __half g_Wh[C3X*DIMM];
__device__ __half g_Wth[DIMM*C3];

// ---------------- helpers ------------------------------------------------------
__device__ __forceinline__ uint32_t smem_u32(const void* p) {
    uint32_t a;
    asm("{ .reg .u64 t; cvta.to.shared.u64 t, %1; cvt.u32.u64 %0, t; }" : "=r"(a) : "l"(p));
    return a;
}
#define CP_ASYNC16(dst_u32, src_ptr) \
    asm volatile("cp.async.cg.shared.global [%0], [%1], 16;" :: "r"(dst_u32), "l"(src_ptr))
#define CP_COMMIT() asm volatile("cp.async.commit_group;" ::: "memory")
#define CP_WAIT1()  asm volatile("cp.async.wait_group 1;" ::: "memory")

// ---------------- fp32 -> fp16 -----------------------------------------------------
__global__ void tohalf(const float* __restrict__ in, __half* __restrict__ out, int n4) {
    int i = blockIdx.x * blockDim.x + threadIdx.x;
    if (i >= n4) return;
    float4 v = ((const float4*)in)[i];
    ((__half2*)out)[i * 2 + 0] = __floats2half2_rn(v.x, v.y);
    ((__half2*)out)[i * 2 + 1] = __floats2half2_rn(v.z, v.w);
}

// ---------------- transpose to fp16: [K,N] -> [N,K] --------------------------------
__global__ void transpose_h(const float* __restrict__ in, __half* __restrict__ outh,
                            int K, int N) {
    __shared__ float t[32][33];
    const int n0 = blockIdx.x * 32, k0 = blockIdx.y * 32;
    const int tx = threadIdx.x & 31, ty = threadIdx.x >> 5;
#pragma unroll
    for (int i = 0; i < 32; i += 8)
        t[ty + i][tx] = in[(size_t)(k0 + ty + i) * N + n0 + tx];
    __syncthreads();
#pragma unroll
    for (int i = 0; i < 32; i += 8)
        outh[(size_t)(n0 + ty + i) * K + k0 + tx] = __float2half(t[tx][ty + i]);
}

// ---------------- bias concat --------------------------------------------------------
__global__ void concat_bias(const float* __restrict__ bq, const float* __restrict__ bk,
                            const float* __restrict__ bv, float* __restrict__ outb) {
    int i = blockIdx.x * blockDim.x + threadIdx.x;
    if (i >= C3X) return;
    outb[i] = (i < OK) ? bq[i] : (i < OV) ? bk[i - OK] : bv[i - OV];
}

// ================= fp16 1-pass HMMA GEMM, BK=32, 2-stage, 2 CTA/SM =================
#define LDT 40
#define HT (128 * LDT * 2)
#define HSTAGE (2 * HT)
#define H_SMEM 65536

__global__ void __launch_bounds__(256, 2)
gemm_h1(const __half* __restrict__ A, const __half* __restrict__ B_g,
        const float* __restrict__ bias, __half* __restrict__ C,
        int M, int N, int K) {
    extern __shared__ char smem[];
    const uint32_t smem_b = smem_u32(smem);
    const int tid = threadIdx.x;
    const int wid = tid >> 5;
    const int wm = wid & 3, wn = wid >> 2;
    const int rowA0 = blockIdx.y * 128;
    const int n0 = blockIdx.x * 128;
    const int nch = K >> 5;

    const int r_cp = tid >> 1;
    const int s_cp = (tid & 1) * 2;
    const __half* srcA = A   + (size_t)(rowA0 + r_cp) * K + s_cp * 8;
    const __half* srcB = B_g + (size_t)(n0 + r_cp) * K + s_cp * 8;
    const uint32_t dst_row = smem_b + r_cp * (LDT * 2) + s_cp * 16;

    auto issue_stage = [&](int c, int buf) {
        const int k0 = c << 5;
        const uint32_t sb = buf * HSTAGE;
        CP_ASYNC16(dst_row + sb, srcA + k0);
        CP_ASYNC16(dst_row + sb + 16, srcA + k0 + 8);
        CP_ASYNC16(dst_row + sb + HT, srcB + k0);
        CP_ASYNC16(dst_row + sb + HT + 16, srcB + k0 + 8);
    };

    wmma::fragment<wmma::accumulator, 16, 16, 16, float> acc[2][4];
#pragma unroll
    for (int i = 0; i < 2; i++)
#pragma unroll
        for (int j = 0; j < 4; j++) wmma::fill_fragment(acc[i][j], 0.f);

    issue_stage(0, 0);
    CP_COMMIT();

    for (int c = 0; c < nch; c++) {
        if (c + 1 < nch) issue_stage(c + 1, (c + 1) & 1);
        CP_COMMIT();
        CP_WAIT1();
        __syncthreads();

        const __half* Ah = (const __half*)(smem + (c & 1) * HSTAGE);
        const __half* Bh = Ah + 128 * LDT;
#pragma unroll
        for (int kk = 0; kk < 32; kk += 16) {
            wmma::fragment<wmma::matrix_a, 16, 16, 16, __half, wmma::row_major> ah[2];
#pragma unroll
            for (int i = 0; i < 2; i++)
                wmma::load_matrix_sync(ah[i], Ah + (wm * 32 + i * 16) * LDT + kk, LDT);
#pragma unroll
            for (int j = 0; j < 4; j++) {
                wmma::fragment<wmma::matrix_b, 16, 16, 16, __half, wmma::col_major> bh;
                wmma::load_matrix_sync(bh, Bh + (wn * 64 + j * 16) * LDT + kk, LDT);
                wmma::mma_sync(acc[0][j], ah[0], bh, acc[0][j]);
                wmma::mma_sync(acc[1][j], ah[1], bh, acc[1][j]);
            }
        }
        __syncthreads();
    }

    float* sC = (float*)smem;
#pragma unroll
    for (int i = 0; i < 2; i++)
#pragma unroll
        for (int j = 0; j < 4; j++)
            wmma::store_matrix_sync(sC + (wm * 32 + i * 16) * 128 + wn * 64 + j * 16,
                                    acc[i][j], 128, wmma::mem_row_major);
    __syncthreads();
#pragma unroll
    for (int i = 0; i < 16; i++) {
        const int f = i * 256 + tid;
        const int r = f >> 5, c4 = f & 31;
        const int gm = rowA0 + r;
        if (gm < M) {
            float4 v = *(float4*)(sC + r * 128 + c4 * 4);
            const int n = n0 + c4 * 4;
            __half2 h0 = __floats2half2_rn(v.x + bias[n + 0], v.y + bias[n + 1]);
            __half2 h1 = __floats2half2_rn(v.z + bias[n + 2], v.w + bias[n + 3]);
            uint2 u;
            u.x = *(uint32_t*)&h0;
            u.y = *(uint32_t*)&h1;
            *(uint2*)(C + (size_t)gm * N + n) = u;
        }
    }
}

// ---------------- inter_cls (fp16 qkv reads) ------------------------------------------
__global__ void inter_cls_kernel() {
    __shared__ float sc[SS];
    __shared__ float red[256];
    __shared__ float part[8 * D3];
    const int h = blockIdx.x, b = blockIdx.y;
    const int tid = threadIdx.x, lane = tid & 31, wid = tid >> 5;
    const __half* baseq = g_qkvh + (size_t)b * SS * C3X + OQ + h * D3;
    const __half* basek = g_qkvh + (size_t)b * SS * C3X + OK + h * D3;
    const __half* basev = g_qkvh + (size_t)b * SS * C3X + OV + h * D3;

    float2 qv[3];
#pragma unroll
    for (int i = 0; i < 3; i++)
        qv[i] = __half22float2(((const __half2*)baseq)[lane + 32 * i]);

    for (int t = wid; t < SS; t += 8) {
        const __half2* kr = (const __half2*)(basek + (size_t)t * C3X);
        float p = 0.f;
#pragma unroll
        for (int i = 0; i < 3; i++) {
            float2 kv = __half22float2(kr[lane + 32 * i]);
            p += qv[i].x * kv.x + qv[i].y * kv.y;
        }
#pragma unroll
        for (int off = 16; off; off >>= 1) p += __shfl_xor_sync(0xffffffffu, p, off);
        if (lane == 0) sc[t] = p * SCALE_INV;
    }
    __syncthreads();

    float m = -1e30f;
    for (int t = tid; t < SS; t += 256) m = fmaxf(m, sc[t]);
    red[tid] = m; __syncthreads();
    for (int s = 128; s; s >>= 1) { if (tid < s) red[tid] = fmaxf(red[tid], red[tid + s]); __syncthreads(); }
    m = red[0]; __syncthreads();

    float z = 0.f;
    for (int t = tid; t < SS; t += 256) { float e = expf(sc[t] - m); sc[t] = e; z += e; }
    red[tid] = z; __syncthreads();
    for (int s = 128; s; s >>= 1) { if (tid < s) red[tid] += red[tid + s]; __syncthreads(); }
    const float invZ = 1.f / red[0];
    __syncthreads();

    float2 a[3] = {{0.f,0.f},{0.f,0.f},{0.f,0.f}};
    for (int t = wid; t < SS; t += 8) {
        const float p = sc[t];
        const __half2* vr = (const __half2*)(basev + (size_t)t * C3X);
#pragma unroll
        for (int i = 0; i < 3; i++) {
            float2 vv = __half22float2(vr[lane + 32 * i]);
            a[i].x += p * vv.x;
            a[i].y += p * vv.y;
        }
    }
#pragma unroll
    for (int i = 0; i < 3; i++) {
        const int j0 = 2 * (lane + 32 * i);
        part[wid * D3 + j0] = a[i].x;
        part[wid * D3 + j0 + 1] = a[i].y;
    }
    __syncthreads();
    if (tid < D3) {
        float s = 0.f;
#pragma unroll
        for (int w = 0; w < 8; w++) s += part[w * D3 + tid];
        g_cls[b * C3 + h * D3 + tid] = s * invZ;
    }
}

// ---------------- temporal attention (fp16 in/out) ------------------------------------
__global__ void temporal_kernel() {
    __shared__ float qs[8 * 193];
    __shared__ float ks[8 * 193];
    __shared__ float sc[8 * 9];
    __shared__ float cw[8];
    const int p = blockIdx.x, h = blockIdx.y, b = blockIdx.z;
    const int tid = threadIdx.x;
    const size_t bb = (size_t)b * SS * C3X;

    for (int e = tid; e < 8 * 96; e += 192) {
        int f = e / 96, j2 = e - f * 96;
        int tok = f * NP + p + 2;
        const __half2* qrow = (const __half2*)(g_qkvh + bb + (size_t)tok * C3X + OQ + h * D3);
        const __half2* krow = (const __half2*)(g_qkvh + bb + (size_t)tok * C3X + OV + h * D3);
        float2 qv = __half22float2(qrow[j2]);
        float2 kv = __half22float2(krow[j2]);
        qs[f * 193 + 2 * j2] = qv.x; qs[f * 193 + 2 * j2 + 1] = qv.y;
        ks[f * 193 + 2 * j2] = kv.x; ks[f * 193 + 2 * j2 + 1] = kv.y;
    }
    __syncthreads();

    if (tid < 64) {
        int f = tid >> 3, g = tid & 7;
        float s = 0.f;
        for (int j = 0; j < D3; j++) s += qs[f * 193 + j] * ks[g * 193 + j];
        sc[f * 9 + g] = s * SCALE_INV;
    }
    __syncthreads();

    if (tid < 8) {
        int f = tid;
        float mx = -1e30f;
        for (int g = 0; g < 8; g++) mx = fmaxf(mx, sc[f * 9 + g]);
        float z = 0.f;
        for (int g = 0; g < 8; g++) { float e = expf(sc[f * 9 + g] - mx); sc[f * 9 + g] = e; z += e; }
        float inv = 1.f / z;
        for (int g = 0; g < 8; g++) sc[f * 9 + g] *= inv;
    }
    __syncthreads();
    if (tid < 8) {
        int g = tid;
        float s = 0.f;
        for (int f = 0; f < 8; f++) s += sc[f * 9 + g];
        cw[g] = s;
    }
    __syncthreads();

    {
        int d = tid;
        float acc = 0.f;
#pragma unroll
        for (int g = 0; g < 8; g++) {
            int tok = g * NP + p + 2;
            acc += cw[g] * __half2float(g_qkvh[bb + (size_t)tok * C3X + OK + h * D3 + d]);
        }
        g_t1h[((size_t)b * PP + p) * C3 + h * D3 + d] = __float2half(acc);
    }
}

// ---------------- output-stage attention (R13 version) ---------------------------------
__global__ void out_attn_kernel(int xi_base, int nk) {
    extern __shared__ float sm[];
    float* Kb = sm;
    float* qb = sm + nk * 193;
    float* w  = qb + 8 * D3;
    const int xi = xi_base + blockIdx.x;
    const int h = blockIdx.y, b = blockIdx.z;
    const int tid = threadIdx.x, lane = tid & 31, wid = tid >> 5;
    const size_t rbase = (size_t)b * PP * C3X + h * D3;
    const int CNT = (nk + 31) >> 5;

    for (int e = tid; e < nk * 96; e += 256) {
        int r = e / 96, j2 = e - r * 96;
        int kp = (nk == 196) ? (r % PP) : (xi + r);
        float2 v = __half22float2(
            *(const __half2*)(g_q2kvh + rbase + (size_t)kp * C3X + OV + 2 * j2));
        Kb[r * 193 + 2 * j2] = v.x;
        Kb[r * 193 + 2 * j2 + 1] = v.y;
    }
    for (int k = tid; k < nk; k += 256) w[k] = 0.f;
    __syncthreads();

    for (int q = wid; q < 196; q += 8) {
        int qp = (xi + q) % PP;
        for (int j2 = lane; j2 < 96; j2 += 32) {
            float2 v = __half22float2(
                *(const __half2*)(g_q2kvh + rbase + (size_t)qp * C3X + OQ + 2 * j2));
            qb[wid * D3 + 2 * j2] = v.x;
            qb[wid * D3 + 2 * j2 + 1] = v.y;
        }
        __syncwarp();

        float s[7];
        int cnt = 0;
        const int kbase = lane * CNT;
        for (int c = 0; c < CNT; c++) {
            const int k = kbase + c;
            if (k < nk) {
                float d = 0.f;
                const float* kr = Kb + k * 193;
                const float* qr = qb + wid * D3;
                for (int j = 0; j < D3; j++) d += qr[j] * kr[j];
                s[cnt++] = d * SCALE_INV;
            }
        }
        float mx = -1e30f;
        for (int c = 0; c < cnt; c++) mx = fmaxf(mx, s[c]);
#pragma unroll
        for (int off = 16; off; off >>= 1) mx = fmaxf(mx, __shfl_xor_sync(0xffffffffu, mx, off));
        float z = 0.f;
        for (int c = 0; c < cnt; c++) { float e = expf(s[c] - mx); s[c] = e; z += e; }
#pragma unroll
        for (int off = 16; off; off >>= 1) z += __shfl_xor_sync(0xffffffffu, z, off);
        float inv = 1.f / z;
        for (int c = 0; c < cnt; c++) atomicAdd(&w[kbase + c], s[c] * inv);
        __syncwarp();
    }
    __syncthreads();

    if (tid < D3) {
        float acc = 0.f;
        for (int k = 0; k < nk; k++) {
            int kp = (nk == 196) ? (k % PP) : (xi + k);
            acc += w[k] * __half2float(g_q2kvh[rbase + (size_t)kp * C3X + OK + tid]);
        }
        g_t2[((size_t)b * FF + xi) * C3 + h * D3 + tid] = acc;
    }
}

// ---------------- final 9 rows per batch ------------------------------------------------
__global__ void final_rows_kernel(const float* __restrict__ Wf, const float* __restrict__ bf) {
    extern __shared__ float As[];
    const int cb = blockIdx.x, b = blockIdx.y;
    const int tid = threadIdx.x;
    for (int e = tid; e < 9 * C3; e += 192) {
        int r = e / C3, k = e - r * C3;
        As[e] = (r == 0) ? g_cls[b * C3 + k] : g_t2[((size_t)b * FF + (r - 1)) * C3 + k];
    }
    __syncthreads();
    const int c = cb * 192 + tid;
    float acc[9];
#pragma unroll
    for (int r = 0; r < 9; r++) acc[r] = 0.f;
    for (int k = 0; k < C3; k++) {
        float wv = Wf[(size_t)k * DIMM + c];
#pragma unroll
        for (int r = 0; r < 9; r++) acc[r] += As[r * C3 + k] * wv;
    }
    float bv = bf[c];
#pragma unroll
    for (int r = 0; r < 9; r++)
        g_rows[((size_t)b * 9 + r) * DIMM + c] = acc[r] + bv;
}

// ---------------- broadcast -> output -----------------------------------------------------
__global__ void bcast_kernel(float* __restrict__ out) {
    size_t i4 = (size_t)blockIdx.x * blockDim.x + threadIdx.x;
    const size_t total4 = (size_t)BB * SS * DIMM / 4;
    if (i4 >= total4) return;
    size_t idx = i4 * 4;
    int c = idx % DIMM;
    size_t rs = idx / DIMM;
    int s = rs % SS;
    int b = rs / SS;
    int r = (s == 0) ? 0 : 1 + ((s - 1) & 7);
    ((float4*)out)[i4] = *(const float4*)(g_rows + ((size_t)b * 9 + r) * DIMM + c);
}

// ---------------- launch: multi-stream fork/join (graph-capturable) ------------------------
extern "C" void kernel_launch(void* const* d_in, const int* in_sizes, int n_in,
                              void* d_out, int out_size) {
    const float* x  = (const float*)d_in[0];
    const float* Wq = (const float*)d_in[1];
    const float* bq = (const float*)d_in[2];
    const float* Wk = (const float*)d_in[3];
    const float* bk = (const float*)d_in[4];
    const float* Wv = (const float*)d_in[5];
    const float* bv = (const float*)d_in[6];
    const float* Wt = (const float*)d_in[7];
    const float* bt = (const float*)d_in[8];
    const float* Wf = (const float*)d_in[9];
    const float* bf = (const float*)d_in[10];
    float* out = (float*)d_out;

    float *p_bqkv;
    cudaGetSymbolAddress((void**)&p_bqkv, g_bqkv);
    __half *p_qkvh, *p_q2kvh, *p_t1h, *p_tih, *p_xh, *p_Wh, *p_Wth;
    cudaGetSymbolAddress((void**)&p_qkvh, g_qkvh);
    cudaGetSymbolAddress((void**)&p_q2kvh, g_q2kvh);
    cudaGetSymbolAddress((void**)&p_t1h, g_t1h);
    cudaGetSymbolAddress((void**)&p_tih, g_tih);
    cudaGetSymbolAddress((void**)&p_xh, g_xh);
    cudaGetSymbolAddress((void**)&p_Wh, g_Wh);
    cudaGetSymbolAddress((void**)&p_Wth, g_Wth);

    cudaFuncSetAttribute(gemm_h1, cudaFuncAttributeMaxDynamicSharedMemorySize, H_SMEM);
    cudaFuncSetAttribute(out_attn_kernel, cudaFuncAttributeMaxDynamicSharedMemorySize, 160000);
    cudaFuncSetAttribute(final_rows_kernel, cudaFuncAttributeMaxDynamicSharedMemorySize, 9 * C3 * 4);

    // persistent side streams + events (host resources; created once, reused)
    static cudaStream_t s1 = nullptr, s2 = nullptr;
    static cudaEvent_t eFork, ePrep, eQKV, eCls, eQ2, eOA8;
    if (!s1) {
        cudaStreamCreateWithFlags(&s1, cudaStreamNonBlocking);
        cudaStreamCreateWithFlags(&s2, cudaStreamNonBlocking);
        cudaEventCreateWithFlags(&eFork, cudaEventDisableTiming);
        cudaEventCreateWithFlags(&ePrep, cudaEventDisableTiming);
        cudaEventCreateWithFlags(&eQKV, cudaEventDisableTiming);
        cudaEventCreateWithFlags(&eCls, cudaEventDisableTiming);
        cudaEventCreateWithFlags(&eQ2, cudaEventDisableTiming);
        cudaEventCreateWithFlags(&eOA8, cudaEventDisableTiming);
    }

    // fork: weight prep on s1, x->fp16 on main
    cudaEventRecord(eFork, 0);
    cudaStreamWaitEvent(s1, eFork, 0);
    transpose_h<<<dim3(C3 / 32, DIMM / 32), 256, 0, s1>>>(Wq, p_Wh + (size_t)OQ * DIMM, DIMM, C3);
    transpose_h<<<dim3(C3 / 32, DIMM / 32), 256, 0, s1>>>(Wk, p_Wh + (size_t)OK * DIMM, DIMM, C3);
    transpose_h<<<dim3(C3 / 32, DIMM / 32), 256, 0, s1>>>(Wv, p_Wh + (size_t)OV * DIMM, DIMM, C3);
    transpose_h<<<dim3(DIMM / 32, C3 / 32), 256, 0, s1>>>(Wt, p_Wth, C3, DIMM);
    concat_bias<<<(C3X + 255) / 256, 256, 0, s1>>>(bq, bk, bv, p_bqkv);
    cudaEventRecord(ePrep, s1);
    {
        int n4 = BB * SS * DIMM / 4;
        tohalf<<<(n4 + 255) / 256, 256>>>(x, p_xh, n4);
    }
    cudaStreamWaitEvent(0, ePrep, 0);

    const int M1 = BB * SS;
    {
        dim3 grid(C3X / 128, M1PAD / 128);
        gemm_h1<<<grid, 256, H_SMEM>>>(p_xh, p_Wh, p_bqkv, p_qkvh, M1, C3X, DIMM);
    }
    cudaEventRecord(eQKV, 0);

    // fork: inter_cls on s1 overlaps temporal -> ti -> q2kv chain on main
    cudaStreamWaitEvent(s1, eQKV, 0);
    inter_cls_kernel<<<dim3(HH, BB), 256, 0, s1>>>();
    cudaEventRecord(eCls, s1);

    temporal_kernel<<<dim3(PP, HH, BB), 192>>>();
    const int M2 = BB * PP;
    {
        dim3 grid(DIMM / 128, M2PAD / 128);
        gemm_h1<<<grid, 256, H_SMEM>>>(p_t1h, p_Wth, bt, p_tih, M2, DIMM, C3);
    }
    {
        dim3 grid(C3X / 128, M2PAD / 128);
        gemm_h1<<<grid, 256, H_SMEM>>>(p_tih, p_Wh, p_bqkv, p_q2kvh, M2, C3X, DIMM);
    }
    cudaEventRecord(eQ2, 0);

    // fork: out_attn(nk=8) on s2 overlaps out_attn(nk=196) on main
    cudaStreamWaitEvent(s2, eQ2, 0);
    {
        size_t smB = (size_t)(8 * 193 + 8 * D3 + 8) * 4;
        out_attn_kernel<<<dim3(7, HH, BB), 256, smB, s2>>>(1, 8);
    }
    cudaEventRecord(eOA8, s2);
    {
        size_t smA = (size_t)(196 * 193 + 8 * D3 + 196) * 4;
        out_attn_kernel<<<dim3(1, HH, BB), 256, smA>>>(0, 196);
    }

    // join all branches before final reduction
    cudaStreamWaitEvent(0, eCls, 0);
    cudaStreamWaitEvent(0, eOA8, 0);
    final_rows_kernel<<<dim3(4, BB), 192, (size_t)9 * C3 * 4>>>(Wf, bf);
    {
        const size_t total4 = (size_t)BB * SS * DIMM / 4;
        bcast_kernel<<<(unsigned)((total4 + 255) / 256), 256>>>(out);
    }
}

// round 16
// speedup vs baseline: 1.1395x; 1.0167x over previous
#include <cuda_runtime.h>
#include <cuda_fp16.h>
#include <mma.h>
#include <cstdint>
#include <math.h>

using namespace nvcuda;

#define HH 12
#define NP 196
#define FF 8
#define DIMM 768
#define D3 192
#define BB 8
#define SS 1569
#define PP 195
#define C3 2304
#define C3X 6912
#define OQ 0
#define OK 2304
#define OV 4608
#define SCALE_INV (1.0f/96.0f)

#define M1PAD 12672
#define M2PAD 1664

// ---------------- scratch (device globals; zero-initialized) ----------------
__device__ __half g_qkvh[BB*SS*C3X];
__device__ __half g_q2kvh[BB*PP*C3X];
__device__ __half g_t1h[M2PAD*C3];
__device__ __half g_tih[M2PAD*DIMM];
__device__ __half g_xh[M1PAD*DIMM];
__device__ float g_cls[BB*C3];
__device__ float g_t2[BB*FF*C3];
__device__ float g_rows[BB*9*DIMM];
__device__ float g_bqkv[C3X];
__device__ __half g_Wh[C3X*DIMM];
__device__ __half g_Wth[DIMM*C3];

// ---------------- helpers ------------------------------------------------------
__device__ __forceinline__ uint32_t smem_u32(const void* p) {
    uint32_t a;
    asm("{ .reg .u64 t; cvta.to.shared.u64 t, %1; cvt.u32.u64 %0, t; }" : "=r"(a) : "l"(p));
    return a;
}
#define CP_ASYNC16(dst_u32, src_ptr) \
    asm volatile("cp.async.cg.shared.global [%0], [%1], 16;" :: "r"(dst_u32), "l"(src_ptr))
#define CP_COMMIT() asm volatile("cp.async.commit_group;" ::: "memory")
#define CP_WAIT1()  asm volatile("cp.async.wait_group 1;" ::: "memory")

// ---------------- fp32 -> fp16 -----------------------------------------------------
__global__ void tohalf(const float* __restrict__ in, __half* __restrict__ out, int n4) {
    int i = blockIdx.x * blockDim.x + threadIdx.x;
    if (i >= n4) return;
    float4 v = ((const float4*)in)[i];
    ((__half2*)out)[i * 2 + 0] = __floats2half2_rn(v.x, v.y);
    ((__half2*)out)[i * 2 + 1] = __floats2half2_rn(v.z, v.w);
}

// ---------------- transpose to fp16: [K,N] -> [N,K] --------------------------------
__global__ void transpose_h(const float* __restrict__ in, __half* __restrict__ outh,
                            int K, int N) {
    __shared__ float t[32][33];
    const int n0 = blockIdx.x * 32, k0 = blockIdx.y * 32;
    const int tx = threadIdx.x & 31, ty = threadIdx.x >> 5;
#pragma unroll
    for (int i = 0; i < 32; i += 8)
        t[ty + i][tx] = in[(size_t)(k0 + ty + i) * N + n0 + tx];
    __syncthreads();
#pragma unroll
    for (int i = 0; i < 32; i += 8)
        outh[(size_t)(n0 + ty + i) * K + k0 + tx] = __float2half(t[tx][ty + i]);
}

// ---------------- bias concat --------------------------------------------------------
__global__ void concat_bias(const float* __restrict__ bq, const float* __restrict__ bk,
                            const float* __restrict__ bv, float* __restrict__ outb) {
    int i = blockIdx.x * blockDim.x + threadIdx.x;
    if (i >= C3X) return;
    outb[i] = (i < OK) ? bq[i] : (i < OV) ? bk[i - OK] : bv[i - OV];
}

// ================= fp16 1-pass HMMA GEMM, BK=32, 2-stage, 2 CTA/SM =================
#define LDT 40
#define HT (128 * LDT * 2)
#define HSTAGE (2 * HT)
#define H_SMEM 65536

__global__ void __launch_bounds__(256, 2)
gemm_h1(const __half* __restrict__ A, const __half* __restrict__ B_g,
        const float* __restrict__ bias, __half* __restrict__ C,
        int M, int N, int K) {
    extern __shared__ char smem[];
    const uint32_t smem_b = smem_u32(smem);
    const int tid = threadIdx.x;
    const int wid = tid >> 5;
    const int wm = wid & 3, wn = wid >> 2;
    const int rowA0 = blockIdx.y * 128;
    const int n0 = blockIdx.x * 128;
    const int nch = K >> 5;

    const int r_cp = tid >> 1;
    const int s_cp = (tid & 1) * 2;
    const __half* srcA = A   + (size_t)(rowA0 + r_cp) * K + s_cp * 8;
    const __half* srcB = B_g + (size_t)(n0 + r_cp) * K + s_cp * 8;
    const uint32_t dst_row = smem_b + r_cp * (LDT * 2) + s_cp * 16;

    auto issue_stage = [&](int c, int buf) {
        const int k0 = c << 5;
        const uint32_t sb = buf * HSTAGE;
        CP_ASYNC16(dst_row + sb, srcA + k0);
        CP_ASYNC16(dst_row + sb + 16, srcA + k0 + 8);
        CP_ASYNC16(dst_row + sb + HT, srcB + k0);
        CP_ASYNC16(dst_row + sb + HT + 16, srcB + k0 + 8);
    };

    wmma::fragment<wmma::accumulator, 16, 16, 16, float> acc[2][4];
#pragma unroll
    for (int i = 0; i < 2; i++)
#pragma unroll
        for (int j = 0; j < 4; j++) wmma::fill_fragment(acc[i][j], 0.f);

    issue_stage(0, 0);
    CP_COMMIT();

    for (int c = 0; c < nch; c++) {
        if (c + 1 < nch) issue_stage(c + 1, (c + 1) & 1);
        CP_COMMIT();
        CP_WAIT1();
        __syncthreads();

        const __half* Ah = (const __half*)(smem + (c & 1) * HSTAGE);
        const __half* Bh = Ah + 128 * LDT;
#pragma unroll
        for (int kk = 0; kk < 32; kk += 16) {
            wmma::fragment<wmma::matrix_a, 16, 16, 16, __half, wmma::row_major> ah[2];
#pragma unroll
            for (int i = 0; i < 2; i++)
                wmma::load_matrix_sync(ah[i], Ah + (wm * 32 + i * 16) * LDT + kk, LDT);
#pragma unroll
            for (int j = 0; j < 4; j++) {
                wmma::fragment<wmma::matrix_b, 16, 16, 16, __half, wmma::col_major> bh;
                wmma::load_matrix_sync(bh, Bh + (wn * 64 + j * 16) * LDT + kk, LDT);
                wmma::mma_sync(acc[0][j], ah[0], bh, acc[0][j]);
                wmma::mma_sync(acc[1][j], ah[1], bh, acc[1][j]);
            }
        }
        __syncthreads();
    }

    float* sC = (float*)smem;
#pragma unroll
    for (int i = 0; i < 2; i++)
#pragma unroll
        for (int j = 0; j < 4; j++)
            wmma::store_matrix_sync(sC + (wm * 32 + i * 16) * 128 + wn * 64 + j * 16,
                                    acc[i][j], 128, wmma::mem_row_major);
    __syncthreads();
#pragma unroll
    for (int i = 0; i < 16; i++) {
        const int f = i * 256 + tid;
        const int r = f >> 5, c4 = f & 31;
        const int gm = rowA0 + r;
        if (gm < M) {
            float4 v = *(float4*)(sC + r * 128 + c4 * 4);
            const int n = n0 + c4 * 4;
            __half2 h0 = __floats2half2_rn(v.x + bias[n + 0], v.y + bias[n + 1]);
            __half2 h1 = __floats2half2_rn(v.z + bias[n + 2], v.w + bias[n + 3]);
            uint2 u;
            u.x = *(uint32_t*)&h0;
            u.y = *(uint32_t*)&h1;
            *(uint2*)(C + (size_t)gm * N + n) = u;
        }
    }
}

// ---------------- inter_cls (fp16 qkv reads) ------------------------------------------
__global__ void inter_cls_kernel() {
    __shared__ float sc[SS];
    __shared__ float red[256];
    __shared__ float part[8 * D3];
    const int h = blockIdx.x, b = blockIdx.y;
    const int tid = threadIdx.x, lane = tid & 31, wid = tid >> 5;
    const __half* baseq = g_qkvh + (size_t)b * SS * C3X + OQ + h * D3;
    const __half* basek = g_qkvh + (size_t)b * SS * C3X + OK + h * D3;
    const __half* basev = g_qkvh + (size_t)b * SS * C3X + OV + h * D3;

    float2 qv[3];
#pragma unroll
    for (int i = 0; i < 3; i++)
        qv[i] = __half22float2(((const __half2*)baseq)[lane + 32 * i]);

    for (int t = wid; t < SS; t += 8) {
        const __half2* kr = (const __half2*)(basek + (size_t)t * C3X);
        float p = 0.f;
#pragma unroll
        for (int i = 0; i < 3; i++) {
            float2 kv = __half22float2(kr[lane + 32 * i]);
            p += qv[i].x * kv.x + qv[i].y * kv.y;
        }
#pragma unroll
        for (int off = 16; off; off >>= 1) p += __shfl_xor_sync(0xffffffffu, p, off);
        if (lane == 0) sc[t] = p * SCALE_INV;
    }
    __syncthreads();

    float m = -1e30f;
    for (int t = tid; t < SS; t += 256) m = fmaxf(m, sc[t]);
    red[tid] = m; __syncthreads();
    for (int s = 128; s; s >>= 1) { if (tid < s) red[tid] = fmaxf(red[tid], red[tid + s]); __syncthreads(); }
    m = red[0]; __syncthreads();

    float z = 0.f;
    for (int t = tid; t < SS; t += 256) { float e = expf(sc[t] - m); sc[t] = e; z += e; }
    red[tid] = z; __syncthreads();
    for (int s = 128; s; s >>= 1) { if (tid < s) red[tid] += red[tid + s]; __syncthreads(); }
    const float invZ = 1.f / red[0];
    __syncthreads();

    float2 a[3] = {{0.f,0.f},{0.f,0.f},{0.f,0.f}};
    for (int t = wid; t < SS; t += 8) {
        const float p = sc[t];
        const __half2* vr = (const __half2*)(basev + (size_t)t * C3X);
#pragma unroll
        for (int i = 0; i < 3; i++) {
            float2 vv = __half22float2(vr[lane + 32 * i]);
            a[i].x += p * vv.x;
            a[i].y += p * vv.y;
        }
    }
#pragma unroll
    for (int i = 0; i < 3; i++) {
        const int j0 = 2 * (lane + 32 * i);
        part[wid * D3 + j0] = a[i].x;
        part[wid * D3 + j0 + 1] = a[i].y;
    }
    __syncthreads();
    if (tid < D3) {
        float s = 0.f;
#pragma unroll
        for (int w = 0; w < 8; w++) s += part[w * D3 + tid];
        g_cls[b * C3 + h * D3 + tid] = s * invZ;
    }
}

// ---------------- temporal attention (fp16 in/out) ------------------------------------
__global__ void temporal_kernel() {
    __shared__ float qs[8 * 193];
    __shared__ float ks[8 * 193];
    __shared__ float sc[8 * 9];
    __shared__ float cw[8];
    const int p = blockIdx.x, h = blockIdx.y, b = blockIdx.z;
    const int tid = threadIdx.x;
    const size_t bb = (size_t)b * SS * C3X;

    for (int e = tid; e < 8 * 96; e += 192) {
        int f = e / 96, j2 = e - f * 96;
        int tok = f * NP + p + 2;
        const __half2* qrow = (const __half2*)(g_qkvh + bb + (size_t)tok * C3X + OQ + h * D3);
        const __half2* krow = (const __half2*)(g_qkvh + bb + (size_t)tok * C3X + OV + h * D3);
        float2 qv = __half22float2(qrow[j2]);
        float2 kv = __half22float2(krow[j2]);
        qs[f * 193 + 2 * j2] = qv.x; qs[f * 193 + 2 * j2 + 1] = qv.y;
        ks[f * 193 + 2 * j2] = kv.x; ks[f * 193 + 2 * j2 + 1] = kv.y;
    }
    __syncthreads();

    if (tid < 64) {
        int f = tid >> 3, g = tid & 7;
        float s = 0.f;
        for (int j = 0; j < D3; j++) s += qs[f * 193 + j] * ks[g * 193 + j];
        sc[f * 9 + g] = s * SCALE_INV;
    }
    __syncthreads();

    if (tid < 8) {
        int f = tid;
        float mx = -1e30f;
        for (int g = 0; g < 8; g++) mx = fmaxf(mx, sc[f * 9 + g]);
        float z = 0.f;
        for (int g = 0; g < 8; g++) { float e = expf(sc[f * 9 + g] - mx); sc[f * 9 + g] = e; z += e; }
        float inv = 1.f / z;
        for (int g = 0; g < 8; g++) sc[f * 9 + g] *= inv;
    }
    __syncthreads();
    if (tid < 8) {
        int g = tid;
        float s = 0.f;
        for (int f = 0; f < 8; f++) s += sc[f * 9 + g];
        cw[g] = s;
    }
    __syncthreads();

    {
        int d = tid;
        float acc = 0.f;
#pragma unroll
        for (int g = 0; g < 8; g++) {
            int tok = g * NP + p + 2;
            acc += cw[g] * __half2float(g_qkvh[bb + (size_t)tok * C3X + OK + h * D3 + d]);
        }
        g_t1h[((size_t)b * PP + p) * C3 + h * D3 + d] = __float2half(acc);
    }
}

// ---------------- output-stage attention (warp-count-generic) --------------------------
__global__ void out_attn_kernel(int xi_base, int nk) {
    extern __shared__ float sm[];
    const int nthr = blockDim.x;
    const int nwarp = nthr >> 5;
    float* Kb = sm;
    float* qb = sm + nk * 193;
    float* w  = qb + nwarp * D3;
    const int xi = xi_base + blockIdx.x;
    const int h = blockIdx.y, b = blockIdx.z;
    const int tid = threadIdx.x, lane = tid & 31, wid = tid >> 5;
    const size_t rbase = (size_t)b * PP * C3X + h * D3;
    const int CNT = (nk + 31) >> 5;

    for (int e = tid; e < nk * 96; e += nthr) {
        int r = e / 96, j2 = e - r * 96;
        int kp = (nk == 196) ? (r % PP) : (xi + r);
        float2 v = __half22float2(
            *(const __half2*)(g_q2kvh + rbase + (size_t)kp * C3X + OV + 2 * j2));
        Kb[r * 193 + 2 * j2] = v.x;
        Kb[r * 193 + 2 * j2 + 1] = v.y;
    }
    for (int k = tid; k < nk; k += nthr) w[k] = 0.f;
    __syncthreads();

    for (int q = wid; q < 196; q += nwarp) {
        int qp = (xi + q) % PP;
        for (int j2 = lane; j2 < 96; j2 += 32) {
            float2 v = __half22float2(
                *(const __half2*)(g_q2kvh + rbase + (size_t)qp * C3X + OQ + 2 * j2));
            qb[wid * D3 + 2 * j2] = v.x;
            qb[wid * D3 + 2 * j2 + 1] = v.y;
        }
        __syncwarp();

        float s[7];
        int cnt = 0;
        const int kbase = lane * CNT;
        for (int c = 0; c < CNT; c++) {
            const int k = kbase + c;
            if (k < nk) {
                float d = 0.f;
                const float* kr = Kb + k * 193;
                const float* qr = qb + wid * D3;
                for (int j = 0; j < D3; j++) d += qr[j] * kr[j];
                s[cnt++] = d * SCALE_INV;
            }
        }
        float mx = -1e30f;
        for (int c = 0; c < cnt; c++) mx = fmaxf(mx, s[c]);
#pragma unroll
        for (int off = 16; off; off >>= 1) mx = fmaxf(mx, __shfl_xor_sync(0xffffffffu, mx, off));
        float z = 0.f;
        for (int c = 0; c < cnt; c++) { float e = expf(s[c] - mx); s[c] = e; z += e; }
#pragma unroll
        for (int off = 16; off; off >>= 1) z += __shfl_xor_sync(0xffffffffu, z, off);
        float inv = 1.f / z;
        for (int c = 0; c < cnt; c++) atomicAdd(&w[kbase + c], s[c] * inv);
        __syncwarp();
    }
    __syncthreads();

    if (tid < D3) {
        float acc = 0.f;
        for (int k = 0; k < nk; k++) {
            int kp = (nk == 196) ? (k % PP) : (xi + k);
            acc += w[k] * __half2float(g_q2kvh[rbase + (size_t)kp * C3X + OK + tid]);
        }
        g_t2[((size_t)b * FF + xi) * C3 + h * D3 + tid] = acc;
    }
}

// ---------------- final 9 rows per batch ------------------------------------------------
__global__ void final_rows_kernel(const float* __restrict__ Wf, const float* __restrict__ bf) {
    extern __shared__ float As[];
    const int cb = blockIdx.x, b = blockIdx.y;
    const int tid = threadIdx.x;
    for (int e = tid; e < 9 * C3; e += 192) {
        int r = e / C3, k = e - r * C3;
        As[e] = (r == 0) ? g_cls[b * C3 + k] : g_t2[((size_t)b * FF + (r - 1)) * C3 + k];
    }
    __syncthreads();
    const int c = cb * 192 + tid;
    float acc[9];
#pragma unroll
    for (int r = 0; r < 9; r++) acc[r] = 0.f;
    for (int k = 0; k < C3; k++) {
        float wv = Wf[(size_t)k * DIMM + c];
#pragma unroll
        for (int r = 0; r < 9; r++) acc[r] += As[r * C3 + k] * wv;
    }
    float bv = bf[c];
#pragma unroll
    for (int r = 0; r < 9; r++)
        g_rows[((size_t)b * 9 + r) * DIMM + c] = acc[r] + bv;
}

// ---------------- broadcast -> output -----------------------------------------------------
__global__ void bcast_kernel(float* __restrict__ out) {
    size_t i4 = (size_t)blockIdx.x * blockDim.x + threadIdx.x;
    const size_t total4 = (size_t)BB * SS * DIMM / 4;
    if (i4 >= total4) return;
    size_t idx = i4 * 4;
    int c = idx % DIMM;
    size_t rs = idx / DIMM;
    int s = rs % SS;
    int b = rs / SS;
    int r = (s == 0) ? 0 : 1 + ((s - 1) & 7);
    ((float4*)out)[i4] = *(const float4*)(g_rows + ((size_t)b * 9 + r) * DIMM + c);
}

// ---------------- launch: multi-stream fork/join (graph-capturable) ------------------------
extern "C" void kernel_launch(void* const* d_in, const int* in_sizes, int n_in,
                              void* d_out, int out_size) {
    const float* x  = (const float*)d_in[0];
    const float* Wq = (const float*)d_in[1];
    const float* bq = (const float*)d_in[2];
    const float* Wk = (const float*)d_in[3];
    const float* bk = (const float*)d_in[4];
    const float* Wv = (const float*)d_in[5];
    const float* bv = (const float*)d_in[6];
    const float* Wt = (const float*)d_in[7];
    const float* bt = (const float*)d_in[8];
    const float* Wf = (const float*)d_in[9];
    const float* bf = (const float*)d_in[10];
    float* out = (float*)d_out;

    float *p_bqkv;
    cudaGetSymbolAddress((void**)&p_bqkv, g_bqkv);
    __half *p_qkvh, *p_q2kvh, *p_t1h, *p_tih, *p_xh, *p_Wh, *p_Wth;
    cudaGetSymbolAddress((void**)&p_qkvh, g_qkvh);
    cudaGetSymbolAddress((void**)&p_q2kvh, g_q2kvh);
    cudaGetSymbolAddress((void**)&p_t1h, g_t1h);
    cudaGetSymbolAddress((void**)&p_tih, g_tih);
    cudaGetSymbolAddress((void**)&p_xh, g_xh);
    cudaGetSymbolAddress((void**)&p_Wh, g_Wh);
    cudaGetSymbolAddress((void**)&p_Wth, g_Wth);

    cudaFuncSetAttribute(gemm_h1, cudaFuncAttributeMaxDynamicSharedMemorySize, H_SMEM);
    cudaFuncSetAttribute(out_attn_kernel, cudaFuncAttributeMaxDynamicSharedMemorySize, 180000);
    cudaFuncSetAttribute(final_rows_kernel, cudaFuncAttributeMaxDynamicSharedMemorySize, 9 * C3 * 4);

    static cudaStream_t s1 = nullptr, s2 = nullptr;
    static cudaEvent_t eFork, ePrep, eQKV, eCls, eQ2, eOA8;
    if (!s1) {
        cudaStreamCreateWithFlags(&s1, cudaStreamNonBlocking);
        cudaStreamCreateWithFlags(&s2, cudaStreamNonBlocking);
        cudaEventCreateWithFlags(&eFork, cudaEventDisableTiming);
        cudaEventCreateWithFlags(&ePrep, cudaEventDisableTiming);
        cudaEventCreateWithFlags(&eQKV, cudaEventDisableTiming);
        cudaEventCreateWithFlags(&eCls, cudaEventDisableTiming);
        cudaEventCreateWithFlags(&eQ2, cudaEventDisableTiming);
        cudaEventCreateWithFlags(&eOA8, cudaEventDisableTiming);
    }

    // fork: weight prep on s1, x->fp16 on main
    cudaEventRecord(eFork, 0);
    cudaStreamWaitEvent(s1, eFork, 0);
    transpose_h<<<dim3(C3 / 32, DIMM / 32), 256, 0, s1>>>(Wq, p_Wh + (size_t)OQ * DIMM, DIMM, C3);
    transpose_h<<<dim3(C3 / 32, DIMM / 32), 256, 0, s1>>>(Wk, p_Wh + (size_t)OK * DIMM, DIMM, C3);
    transpose_h<<<dim3(C3 / 32, DIMM / 32), 256, 0, s1>>>(Wv, p_Wh + (size_t)OV * DIMM, DIMM, C3);
    transpose_h<<<dim3(DIMM / 32, C3 / 32), 256, 0, s1>>>(Wt, p_Wth, C3, DIMM);
    concat_bias<<<(C3X + 255) / 256, 256, 0, s1>>>(bq, bk, bv, p_bqkv);
    cudaEventRecord(ePrep, s1);
    {
        int n4 = BB * SS * DIMM / 4;
        tohalf<<<(n4 + 255) / 256, 256>>>(x, p_xh, n4);
    }
    cudaStreamWaitEvent(0, ePrep, 0);

    const int M1 = BB * SS;
    {
        dim3 grid(C3X / 128, M1PAD / 128);
        gemm_h1<<<grid, 256, H_SMEM>>>(p_xh, p_Wh, p_bqkv, p_qkvh, M1, C3X, DIMM);
    }
    cudaEventRecord(eQKV, 0);

    // fork: inter_cls on s1 overlaps temporal -> ti -> q2kv chain on main
    cudaStreamWaitEvent(s1, eQKV, 0);
    inter_cls_kernel<<<dim3(HH, BB), 256, 0, s1>>>();
    cudaEventRecord(eCls, s1);

    temporal_kernel<<<dim3(PP, HH, BB), 192>>>();
    const int M2 = BB * PP;
    {
        dim3 grid(DIMM / 128, M2PAD / 128);
        gemm_h1<<<grid, 256, H_SMEM>>>(p_t1h, p_Wth, bt, p_tih, M2, DIMM, C3);
    }
    {
        dim3 grid(C3X / 128, M2PAD / 128);
        gemm_h1<<<grid, 256, H_SMEM>>>(p_tih, p_Wh, p_bqkv, p_q2kvh, M2, C3X, DIMM);
    }
    cudaEventRecord(eQ2, 0);

    // fork: out_attn(nk=8) on s2 overlaps out_attn(nk=196, 1024 threads) on main
    cudaStreamWaitEvent(s2, eQ2, 0);
    {
        size_t smB = (size_t)(8 * 193 + 8 * D3 + 8) * 4;
        out_attn_kernel<<<dim3(7, HH, BB), 256, smB, s2>>>(1, 8);
    }
    cudaEventRecord(eOA8, s2);
    {
        size_t smA = (size_t)(196 * 193 + 32 * D3 + 196) * 4;   // 176672
        out_attn_kernel<<<dim3(1, HH, BB), 1024, smA>>>(0, 196);
    }

    // join all branches before final reduction
    cudaStreamWaitEvent(0, eCls, 0);
    cudaStreamWaitEvent(0, eOA8, 0);
    final_rows_kernel<<<dim3(4, BB), 192, (size_t)9 * C3 * 4>>>(Wf, bf);
    {
        const size_t total4 = (size_t)BB * SS * DIMM / 4;
        bcast_kernel<<<(unsigned)((total4 + 255) / 256), 256>>>(out);
    }
}

// round 17
// speedup vs baseline: 1.1520x; 1.0109x over previous
#include <cuda_runtime.h>
#include <cuda_fp16.h>
#include <mma.h>
#include <cstdint>
#include <math.h>

using namespace nvcuda;

#define HH 12
#define NP 196
#define FF 8
#define DIMM 768
#define D3 192
#define BB 8
#define SS 1569
#define PP 195
#define C3 2304
#define C3X 6912
#define OQ 0
#define OK 2304
#define OV 4608
#define SCALE_INV (1.0f/96.0f)

#define M1PAD 12672
#define M2PAD 1664

// ---------------- scratch (device globals; zero-initialized) ----------------
__device__ __half g_qkvh[BB*SS*C3X];
__device__ __half g_q2kvh[BB*PP*C3X];
__device__ __half g_t1h[M2PAD*C3];
__device__ __half g_tih[M2PAD*DIMM];
__device__ __half g_xh[M1PAD*DIMM];
__device__ float g_cls[BB*C3];
__device__ float g_t2[BB*FF*C3];
__device__ float g_rows[BB*9*DIMM];
__device__ float g_bqkv[C3X];
__device__ __half g_Wh[C3X*DIMM];
__device__ __half g_Wth[DIMM*C3];

// ---------------- helpers ------------------------------------------------------
__device__ __forceinline__ uint32_t smem_u32(const void* p) {
    uint32_t a;
    asm("{ .reg .u64 t; cvta.to.shared.u64 t, %1; cvt.u32.u64 %0, t; }" : "=r"(a) : "l"(p));
    return a;
}
#define CP_ASYNC16(dst_u32, src_ptr) \
    asm volatile("cp.async.cg.shared.global [%0], [%1], 16;" :: "r"(dst_u32), "l"(src_ptr))
#define CP_COMMIT() asm volatile("cp.async.commit_group;" ::: "memory")
#define CP_WAITG1() asm volatile("cp.async.wait_group 1;" ::: "memory")

// ---------------- fp32 -> fp16 -----------------------------------------------------
__global__ void tohalf(const float* __restrict__ in, __half* __restrict__ out, int n4) {
    int i = blockIdx.x * blockDim.x + threadIdx.x;
    if (i >= n4) return;
    float4 v = ((const float4*)in)[i];
    ((__half2*)out)[i * 2 + 0] = __floats2half2_rn(v.x, v.y);
    ((__half2*)out)[i * 2 + 1] = __floats2half2_rn(v.z, v.w);
}

// ---------------- transpose to fp16: [K,N] -> [N,K] --------------------------------
__global__ void transpose_h(const float* __restrict__ in, __half* __restrict__ outh,
                            int K, int N) {
    __shared__ float t[32][33];
    const int n0 = blockIdx.x * 32, k0 = blockIdx.y * 32;
    const int tx = threadIdx.x & 31, ty = threadIdx.x >> 5;
#pragma unroll
    for (int i = 0; i < 32; i += 8)
        t[ty + i][tx] = in[(size_t)(k0 + ty + i) * N + n0 + tx];
    __syncthreads();
#pragma unroll
    for (int i = 0; i < 32; i += 8)
        outh[(size_t)(n0 + ty + i) * K + k0 + tx] = __float2half(t[tx][ty + i]);
}

// ---------------- bias concat --------------------------------------------------------
__global__ void concat_bias(const float* __restrict__ bq, const float* __restrict__ bk,
                            const float* __restrict__ bv, float* __restrict__ outb) {
    int i = blockIdx.x * blockDim.x + threadIdx.x;
    if (i >= C3X) return;
    outb[i] = (i < OK) ? bq[i] : (i < OV) ? bk[i - OK] : bv[i - OV];
}

// ====== fp16 1-pass HMMA GEMM, BK=32, 3-stage cp.async, ONE barrier/chunk ==========
#define LDT 40
#define HT (128 * LDT * 2)          // 10240 bytes per fp16 tile
#define HSTAGE (2 * HT)             // A | B = 20480 per stage; 3 stages = 61440
#define H_SMEM 65536                // epilogue staging needs 128*128*4

__global__ void __launch_bounds__(256, 2)
gemm_h1(const __half* __restrict__ A, const __half* __restrict__ B_g,
        const float* __restrict__ bias, __half* __restrict__ C,
        int M, int N, int K) {
    extern __shared__ char smem[];
    const uint32_t smem_b = smem_u32(smem);
    const int tid = threadIdx.x;
    const int wid = tid >> 5;
    const int wm = wid & 3, wn = wid >> 2;
    const int rowA0 = blockIdx.y * 128;
    const int n0 = blockIdx.x * 128;
    const int nch = K >> 5;

    const int r_cp = tid >> 1;
    const int s_cp = (tid & 1) * 2;
    const __half* srcA = A   + (size_t)(rowA0 + r_cp) * K + s_cp * 8;
    const __half* srcB = B_g + (size_t)(n0 + r_cp) * K + s_cp * 8;
    const uint32_t dst_row = smem_b + r_cp * (LDT * 2) + s_cp * 16;

    auto issue_stage = [&](int c, int buf) {
        const int k0 = c << 5;
        const uint32_t sb = buf * HSTAGE;
        CP_ASYNC16(dst_row + sb, srcA + k0);
        CP_ASYNC16(dst_row + sb + 16, srcA + k0 + 8);
        CP_ASYNC16(dst_row + sb + HT, srcB + k0);
        CP_ASYNC16(dst_row + sb + HT + 16, srcB + k0 + 8);
    };

    wmma::fragment<wmma::accumulator, 16, 16, 16, float> acc[2][4];
#pragma unroll
    for (int i = 0; i < 2; i++)
#pragma unroll
        for (int j = 0; j < 4; j++) wmma::fill_fragment(acc[i][j], 0.f);

    // prologue: stages 0 and 1
    issue_stage(0, 0);
    CP_COMMIT();
    if (nch > 1) issue_stage(1, 1);
    CP_COMMIT();

    int buf2 = 2;   // buffer for stage c+2 (rotates 2,0,1,2,...)
    for (int c = 0; c < nch; c++) {
        CP_WAITG1();          // stage c arrived (<=1 group pending)
        __syncthreads();      // all warps done reading stage c-1's buffer
        if (c + 2 < nch) issue_stage(c + 2, buf2);
        CP_COMMIT();
        buf2 = (buf2 == 2) ? 0 : buf2 + 1;

        const int bc = c % 3;
        const __half* Ah = (const __half*)(smem + bc * HSTAGE);
        const __half* Bh = Ah + 128 * LDT;
#pragma unroll
        for (int kk = 0; kk < 32; kk += 16) {
            wmma::fragment<wmma::matrix_a, 16, 16, 16, __half, wmma::row_major> ah[2];
#pragma unroll
            for (int i = 0; i < 2; i++)
                wmma::load_matrix_sync(ah[i], Ah + (wm * 32 + i * 16) * LDT + kk, LDT);
#pragma unroll
            for (int j = 0; j < 4; j++) {
                wmma::fragment<wmma::matrix_b, 16, 16, 16, __half, wmma::col_major> bh;
                wmma::load_matrix_sync(bh, Bh + (wn * 64 + j * 16) * LDT + kk, LDT);
                wmma::mma_sync(acc[0][j], ah[0], bh, acc[0][j]);
                wmma::mma_sync(acc[1][j], ah[1], bh, acc[1][j]);
            }
        }
    }
    __syncthreads();   // protect epilogue smem reuse

    float* sC = (float*)smem;
#pragma unroll
    for (int i = 0; i < 2; i++)
#pragma unroll
        for (int j = 0; j < 4; j++)
            wmma::store_matrix_sync(sC + (wm * 32 + i * 16) * 128 + wn * 64 + j * 16,
                                    acc[i][j], 128, wmma::mem_row_major);
    __syncthreads();
#pragma unroll
    for (int i = 0; i < 16; i++) {
        const int f = i * 256 + tid;
        const int r = f >> 5, c4 = f & 31;
        const int gm = rowA0 + r;
        if (gm < M) {
            float4 v = *(float4*)(sC + r * 128 + c4 * 4);
            const int n = n0 + c4 * 4;
            __half2 h0 = __floats2half2_rn(v.x + bias[n + 0], v.y + bias[n + 1]);
            __half2 h1 = __floats2half2_rn(v.z + bias[n + 2], v.w + bias[n + 3]);
            uint2 u;
            u.x = *(uint32_t*)&h0;
            u.y = *(uint32_t*)&h1;
            *(uint2*)(C + (size_t)gm * N + n) = u;
        }
    }
}

// ---------------- inter_cls (fp16 qkv reads) ------------------------------------------
__global__ void inter_cls_kernel() {
    __shared__ float sc[SS];
    __shared__ float red[256];
    __shared__ float part[8 * D3];
    const int h = blockIdx.x, b = blockIdx.y;
    const int tid = threadIdx.x, lane = tid & 31, wid = tid >> 5;
    const __half* baseq = g_qkvh + (size_t)b * SS * C3X + OQ + h * D3;
    const __half* basek = g_qkvh + (size_t)b * SS * C3X + OK + h * D3;
    const __half* basev = g_qkvh + (size_t)b * SS * C3X + OV + h * D3;

    float2 qv[3];
#pragma unroll
    for (int i = 0; i < 3; i++)
        qv[i] = __half22float2(((const __half2*)baseq)[lane + 32 * i]);

    for (int t = wid; t < SS; t += 8) {
        const __half2* kr = (const __half2*)(basek + (size_t)t * C3X);
        float p = 0.f;
#pragma unroll
        for (int i = 0; i < 3; i++) {
            float2 kv = __half22float2(kr[lane + 32 * i]);
            p += qv[i].x * kv.x + qv[i].y * kv.y;
        }
#pragma unroll
        for (int off = 16; off; off >>= 1) p += __shfl_xor_sync(0xffffffffu, p, off);
        if (lane == 0) sc[t] = p * SCALE_INV;
    }
    __syncthreads();

    float m = -1e30f;
    for (int t = tid; t < SS; t += 256) m = fmaxf(m, sc[t]);
    red[tid] = m; __syncthreads();
    for (int s = 128; s; s >>= 1) { if (tid < s) red[tid] = fmaxf(red[tid], red[tid + s]); __syncthreads(); }
    m = red[0]; __syncthreads();

    float z = 0.f;
    for (int t = tid; t < SS; t += 256) { float e = expf(sc[t] - m); sc[t] = e; z += e; }
    red[tid] = z; __syncthreads();
    for (int s = 128; s; s >>= 1) { if (tid < s) red[tid] += red[tid + s]; __syncthreads(); }
    const float invZ = 1.f / red[0];
    __syncthreads();

    float2 a[3] = {{0.f,0.f},{0.f,0.f},{0.f,0.f}};
    for (int t = wid; t < SS; t += 8) {
        const float p = sc[t];
        const __half2* vr = (const __half2*)(basev + (size_t)t * C3X);
#pragma unroll
        for (int i = 0; i < 3; i++) {
            float2 vv = __half22float2(vr[lane + 32 * i]);
            a[i].x += p * vv.x;
            a[i].y += p * vv.y;
        }
    }
#pragma unroll
    for (int i = 0; i < 3; i++) {
        const int j0 = 2 * (lane + 32 * i);
        part[wid * D3 + j0] = a[i].x;
        part[wid * D3 + j0 + 1] = a[i].y;
    }
    __syncthreads();
    if (tid < D3) {
        float s = 0.f;
#pragma unroll
        for (int w = 0; w < 8; w++) s += part[w * D3 + tid];
        g_cls[b * C3 + h * D3 + tid] = s * invZ;
    }
}

// ---------------- temporal attention (fp16 in/out) ------------------------------------
__global__ void temporal_kernel() {
    __shared__ float qs[8 * 193];
    __shared__ float ks[8 * 193];
    __shared__ float sc[8 * 9];
    __shared__ float cw[8];
    const int p = blockIdx.x, h = blockIdx.y, b = blockIdx.z;
    const int tid = threadIdx.x;
    const size_t bb = (size_t)b * SS * C3X;

    for (int e = tid; e < 8 * 96; e += 192) {
        int f = e / 96, j2 = e - f * 96;
        int tok = f * NP + p + 2;
        const __half2* qrow = (const __half2*)(g_qkvh + bb + (size_t)tok * C3X + OQ + h * D3);
        const __half2* krow = (const __half2*)(g_qkvh + bb + (size_t)tok * C3X + OV + h * D3);
        float2 qv = __half22float2(qrow[j2]);
        float2 kv = __half22float2(krow[j2]);
        qs[f * 193 + 2 * j2] = qv.x; qs[f * 193 + 2 * j2 + 1] = qv.y;
        ks[f * 193 + 2 * j2] = kv.x; ks[f * 193 + 2 * j2 + 1] = kv.y;
    }
    __syncthreads();

    if (tid < 64) {
        int f = tid >> 3, g = tid & 7;
        float s = 0.f;
        for (int j = 0; j < D3; j++) s += qs[f * 193 + j] * ks[g * 193 + j];
        sc[f * 9 + g] = s * SCALE_INV;
    }
    __syncthreads();

    if (tid < 8) {
        int f = tid;
        float mx = -1e30f;
        for (int g = 0; g < 8; g++) mx = fmaxf(mx, sc[f * 9 + g]);
        float z = 0.f;
        for (int g = 0; g < 8; g++) { float e = expf(sc[f * 9 + g] - mx); sc[f * 9 + g] = e; z += e; }
        float inv = 1.f / z;
        for (int g = 0; g < 8; g++) sc[f * 9 + g] *= inv;
    }
    __syncthreads();
    if (tid < 8) {
        int g = tid;
        float s = 0.f;
        for (int f = 0; f < 8; f++) s += sc[f * 9 + g];
        cw[g] = s;
    }
    __syncthreads();

    {
        int d = tid;
        float acc = 0.f;
#pragma unroll
        for (int g = 0; g < 8; g++) {
            int tok = g * NP + p + 2;
            acc += cw[g] * __half2float(g_qkvh[bb + (size_t)tok * C3X + OK + h * D3 + d]);
        }
        g_t1h[((size_t)b * PP + p) * C3 + h * D3 + d] = __float2half(acc);
    }
}

// ---------------- output-stage attention (warp-count-generic) --------------------------
__global__ void out_attn_kernel(int xi_base, int nk) {
    extern __shared__ float sm[];
    const int nthr = blockDim.x;
    const int nwarp = nthr >> 5;
    float* Kb = sm;
    float* qb = sm + nk * 193;
    float* w  = qb + nwarp * D3;
    const int xi = xi_base + blockIdx.x;
    const int h = blockIdx.y, b = blockIdx.z;
    const int tid = threadIdx.x, lane = tid & 31, wid = tid >> 5;
    const size_t rbase = (size_t)b * PP * C3X + h * D3;
    const int CNT = (nk + 31) >> 5;

    for (int e = tid; e < nk * 96; e += nthr) {
        int r = e / 96, j2 = e - r * 96;
        int kp = (nk == 196) ? (r % PP) : (xi + r);
        float2 v = __half22float2(
            *(const __half2*)(g_q2kvh + rbase + (size_t)kp * C3X + OV + 2 * j2));
        Kb[r * 193 + 2 * j2] = v.x;
        Kb[r * 193 + 2 * j2 + 1] = v.y;
    }
    for (int k = tid; k < nk; k += nthr) w[k] = 0.f;
    __syncthreads();

    for (int q = wid; q < 196; q += nwarp) {
        int qp = (xi + q) % PP;
        for (int j2 = lane; j2 < 96; j2 += 32) {
            float2 v = __half22float2(
                *(const __half2*)(g_q2kvh + rbase + (size_t)qp * C3X + OQ + 2 * j2));
            qb[wid * D3 + 2 * j2] = v.x;
            qb[wid * D3 + 2 * j2 + 1] = v.y;
        }
        __syncwarp();

        float s[7];
        int cnt = 0;
        const int kbase = lane * CNT;
        for (int c = 0; c < CNT; c++) {
            const int k = kbase + c;
            if (k < nk) {
                float d = 0.f;
                const float* kr = Kb + k * 193;
                const float* qr = qb + wid * D3;
                for (int j = 0; j < D3; j++) d += qr[j] * kr[j];
                s[cnt++] = d * SCALE_INV;
            }
        }
        float mx = -1e30f;
        for (int c = 0; c < cnt; c++) mx = fmaxf(mx, s[c]);
#pragma unroll
        for (int off = 16; off; off >>= 1) mx = fmaxf(mx, __shfl_xor_sync(0xffffffffu, mx, off));
        float z = 0.f;
        for (int c = 0; c < cnt; c++) { float e = expf(s[c] - mx); s[c] = e; z += e; }
#pragma unroll
        for (int off = 16; off; off >>= 1) z += __shfl_xor_sync(0xffffffffu, z, off);
        float inv = 1.f / z;
        for (int c = 0; c < cnt; c++) atomicAdd(&w[kbase + c], s[c] * inv);
        __syncwarp();
    }
    __syncthreads();

    if (tid < D3) {
        float acc = 0.f;
        for (int k = 0; k < nk; k++) {
            int kp = (nk == 196) ? (k % PP) : (xi + k);
            acc += w[k] * __half2float(g_q2kvh[rbase + (size_t)kp * C3X + OK + tid]);
        }
        g_t2[((size_t)b * FF + xi) * C3 + h * D3 + tid] = acc;
    }
}

// ---------------- final 9 rows per batch ------------------------------------------------
__global__ void final_rows_kernel(const float* __restrict__ Wf, const float* __restrict__ bf) {
    extern __shared__ float As[];
    const int cb = blockIdx.x, b = blockIdx.y;
    const int tid = threadIdx.x;
    for (int e = tid; e < 9 * C3; e += 192) {
        int r = e / C3, k = e - r * C3;
        As[e] = (r == 0) ? g_cls[b * C3 + k] : g_t2[((size_t)b * FF + (r - 1)) * C3 + k];
    }
    __syncthreads();
    const int c = cb * 192 + tid;
    float acc[9];
#pragma unroll
    for (int r = 0; r < 9; r++) acc[r] = 0.f;
    for (int k = 0; k < C3; k++) {
        float wv = Wf[(size_t)k * DIMM + c];
#pragma unroll
        for (int r = 0; r < 9; r++) acc[r] += As[r * C3 + k] * wv;
    }
    float bv = bf[c];
#pragma unroll
    for (int r = 0; r < 9; r++)
        g_rows[((size_t)b * 9 + r) * DIMM + c] = acc[r] + bv;
}

// ---------------- broadcast -> output -----------------------------------------------------
__global__ void bcast_kernel(float* __restrict__ out) {
    size_t i4 = (size_t)blockIdx.x * blockDim.x + threadIdx.x;
    const size_t total4 = (size_t)BB * SS * DIMM / 4;
    if (i4 >= total4) return;
    size_t idx = i4 * 4;
    int c = idx % DIMM;
    size_t rs = idx / DIMM;
    int s = rs % SS;
    int b = rs / SS;
    int r = (s == 0) ? 0 : 1 + ((s - 1) & 7);
    ((float4*)out)[i4] = *(const float4*)(g_rows + ((size_t)b * 9 + r) * DIMM + c);
}

// ---------------- launch: multi-stream fork/join (graph-capturable) ------------------------
extern "C" void kernel_launch(void* const* d_in, const int* in_sizes, int n_in,
                              void* d_out, int out_size) {
    const float* x  = (const float*)d_in[0];
    const float* Wq = (const float*)d_in[1];
    const float* bq = (const float*)d_in[2];
    const float* Wk = (const float*)d_in[3];
    const float* bk = (const float*)d_in[4];
    const float* Wv = (const float*)d_in[5];
    const float* bv = (const float*)d_in[6];
    const float* Wt = (const float*)d_in[7];
    const float* bt = (const float*)d_in[8];
    const float* Wf = (const float*)d_in[9];
    const float* bf = (const float*)d_in[10];
    float* out = (float*)d_out;

    float *p_bqkv;
    cudaGetSymbolAddress((void**)&p_bqkv, g_bqkv);
    __half *p_qkvh, *p_q2kvh, *p_t1h, *p_tih, *p_xh, *p_Wh, *p_Wth;
    cudaGetSymbolAddress((void**)&p_qkvh, g_qkvh);
    cudaGetSymbolAddress((void**)&p_q2kvh, g_q2kvh);
    cudaGetSymbolAddress((void**)&p_t1h, g_t1h);
    cudaGetSymbolAddress((void**)&p_tih, g_tih);
    cudaGetSymbolAddress((void**)&p_xh, g_xh);
    cudaGetSymbolAddress((void**)&p_Wh, g_Wh);
    cudaGetSymbolAddress((void**)&p_Wth, g_Wth);

    cudaFuncSetAttribute(gemm_h1, cudaFuncAttributeMaxDynamicSharedMemorySize, H_SMEM);
    cudaFuncSetAttribute(out_attn_kernel, cudaFuncAttributeMaxDynamicSharedMemorySize, 180000);
    cudaFuncSetAttribute(final_rows_kernel, cudaFuncAttributeMaxDynamicSharedMemorySize, 9 * C3 * 4);

    static cudaStream_t s1 = nullptr, s2 = nullptr;
    static cudaEvent_t eFork, ePrep, eQKV, eCls, eQ2, eOA8;
    if (!s1) {
        cudaStreamCreateWithFlags(&s1, cudaStreamNonBlocking);
        cudaStreamCreateWithFlags(&s2, cudaStreamNonBlocking);
        cudaEventCreateWithFlags(&eFork, cudaEventDisableTiming);
        cudaEventCreateWithFlags(&ePrep, cudaEventDisableTiming);
        cudaEventCreateWithFlags(&eQKV, cudaEventDisableTiming);
        cudaEventCreateWithFlags(&eCls, cudaEventDisableTiming);
        cudaEventCreateWithFlags(&eQ2, cudaEventDisableTiming);
        cudaEventCreateWithFlags(&eOA8, cudaEventDisableTiming);
    }

    // fork: weight prep on s1, x->fp16 on main
    cudaEventRecord(eFork, 0);
    cudaStreamWaitEvent(s1, eFork, 0);
    transpose_h<<<dim3(C3 / 32, DIMM / 32), 256, 0, s1>>>(Wq, p_Wh + (size_t)OQ * DIMM, DIMM, C3);
    transpose_h<<<dim3(C3 / 32, DIMM / 32), 256, 0, s1>>>(Wk, p_Wh + (size_t)OK * DIMM, DIMM, C3);
    transpose_h<<<dim3(C3 / 32, DIMM / 32), 256, 0, s1>>>(Wv, p_Wh + (size_t)OV * DIMM, DIMM, C3);
    transpose_h<<<dim3(DIMM / 32, C3 / 32), 256, 0, s1>>>(Wt, p_Wth, C3, DIMM);
    concat_bias<<<(C3X + 255) / 256, 256, 0, s1>>>(bq, bk, bv, p_bqkv);
    cudaEventRecord(ePrep, s1);
    {
        int n4 = BB * SS * DIMM / 4;
        tohalf<<<(n4 + 255) / 256, 256>>>(x, p_xh, n4);
    }
    cudaStreamWaitEvent(0, ePrep, 0);

    const int M1 = BB * SS;
    {
        dim3 grid(C3X / 128, M1PAD / 128);
        gemm_h1<<<grid, 256, H_SMEM>>>(p_xh, p_Wh, p_bqkv, p_qkvh, M1, C3X, DIMM);
    }
    cudaEventRecord(eQKV, 0);

    // fork: inter_cls on s1 overlaps temporal -> ti -> q2kv chain on main
    cudaStreamWaitEvent(s1, eQKV, 0);
    inter_cls_kernel<<<dim3(HH, BB), 256, 0, s1>>>();
    cudaEventRecord(eCls, s1);

    temporal_kernel<<<dim3(PP, HH, BB), 192>>>();
    const int M2 = BB * PP;
    {
        dim3 grid(DIMM / 128, M2PAD / 128);
        gemm_h1<<<grid, 256, H_SMEM>>>(p_t1h, p_Wth, bt, p_tih, M2, DIMM, C3);
    }
    {
        dim3 grid(C3X / 128, M2PAD / 128);
        gemm_h1<<<grid, 256, H_SMEM>>>(p_tih, p_Wh, p_bqkv, p_q2kvh, M2, C3X, DIMM);
    }
    cudaEventRecord(eQ2, 0);

    // fork: out_attn(nk=8) on s2 overlaps out_attn(nk=196, 1024 threads) on main
    cudaStreamWaitEvent(s2, eQ2, 0);
    {
        size_t smB = (size_t)(8 * 193 + 8 * D3 + 8) * 4;
        out_attn_kernel<<<dim3(7, HH, BB), 256, smB, s2>>>(1, 8);
    }
    cudaEventRecord(eOA8, s2);
    {
        size_t smA = (size_t)(196 * 193 + 32 * D3 + 196) * 4;
        out_attn_kernel<<<dim3(1, HH, BB), 1024, smA>>>(0, 196);
    }

    // join all branches before final reduction
    cudaStreamWaitEvent(0, eCls, 0);
    cudaStreamWaitEvent(0, eOA8, 0);
    final_rows_kernel<<<dim3(4, BB), 192, (size_t)9 * C3 * 4>>>(Wf, bf);
    {
        const size_t total4 = (size_t)BB * SS * DIMM / 4;
        bcast_kernel<<<(unsigned)((total4 + 255) / 256), 256>>>(out);
    }
}